// round 9
// baseline (speedup 1.0000x reference)
#include <cuda_runtime.h>
#include <cuda_bf16.h>
#include <stdint.h>

#define Bq 4
#define Tq 2048
#define Dq 1024
#define Hq 16
#define Sq 64
#define Cq 64
#define NTq (Bq*Tq)      // 8192 rows
#define NCq (Tq/Cq)      // 32 chunks
#define BHq (Bq*Hq)      // 64 (b,h) pairs

// ---------------- scratch (static __device__, allocation-free) ----------------
__device__ __nv_bfloat16 g_Wb[5][Dq*Dq];   // ternary weights as bf16 (-1,0,1)
__device__ float  g_wpart[5][64];
__device__ float  g_wscale[5];
__device__ __nv_bfloat16 g_Xb[5][NTq*Dq];  // quantized activations as bf16 ints
__device__ float  g_xscale[5][NTq];
__device__ float  g_Y[4][NTq*Dq];          // r,k,v,g projection outputs (fp32)
__device__ float  g_states[BHq*NCq*Sq*Sq]; // per-chunk contributions -> states
__device__ float  g_ywkv[NTq*Dq];          // wkv output in (B,T,D)
// decay tables: [h][t][s], bit-exact replicas of the per-block exp computations
__device__ float  g_ein[Hq*Cq*Sq];         // exp(-t*lw)
__device__ float  g_ekt[Hq*Cq*Sq];         // exp(t*lw)
__device__ float  g_ek1[Hq*Cq*Sq];         // exp((t+1)*lw)
__device__ float  g_ekc[Hq*Cq*Sq];         // exp((C-1-t)*lw)
__device__ float  g_uex[Hq*Sq];            // exp(u)
__device__ float  g_wCt[Hq*Sq];            // exp(C*lw)

// ---------------- compensated-sum helpers ----------------
__device__ __forceinline__ float2 df_comb(float2 a, float2 b){
  float s  = a.x + b.x;
  float bp = s - a.x;
  float er = (a.x - (s - bp)) + (b.x - bp);
  return make_float2(s, a.y + b.y + er);
}
__device__ __forceinline__ void df_acc(float2& s, float v){
  float t=s.x+v; float bp=t-s.x; float er=(s.x-(t-bp))+(v-bp);
  s.x=t; s.y+=er;
}
__device__ __forceinline__ float2 shfl2(float2 v, int o){
  return make_float2(__shfl_xor_sync(0xffffffffu,v.x,o),
                     __shfl_xor_sync(0xffffffffu,v.y,o));
}
// 3-sync block reductions over 256 threads (8 warps)
__device__ __forceinline__ void block_sum2(float2& a, float2& b, float2* r1, float2* r2, int tid){
  #pragma unroll
  for(int o=16;o;o>>=1){ a=df_comb(a,shfl2(a,o)); b=df_comb(b,shfl2(b,o)); }
  __syncthreads();
  if((tid&31)==0){ r1[tid>>5]=a; r2[tid>>5]=b; }
  __syncthreads();
  if(tid<32){
    float2 aa=(tid<8)?r1[tid]:make_float2(0.f,0.f);
    float2 bb=(tid<8)?r2[tid]:make_float2(0.f,0.f);
    #pragma unroll
    for(int o=4;o;o>>=1){ aa=df_comb(aa,shfl2(aa,o)); bb=df_comb(bb,shfl2(bb,o)); }
    if(tid==0){ r1[0]=aa; r2[0]=bb; }
  }
  __syncthreads();
  a=r1[0]; b=r2[0];
}
__device__ __forceinline__ void block_sum1(float2& a, float2* r1, int tid){
  #pragma unroll
  for(int o=16;o;o>>=1) a=df_comb(a,shfl2(a,o));
  __syncthreads();
  if((tid&31)==0) r1[tid>>5]=a;
  __syncthreads();
  if(tid<32){
    float2 aa=(tid<8)?r1[tid]:make_float2(0.f,0.f);
    #pragma unroll
    for(int o=4;o;o>>=1) aa=df_comb(aa,shfl2(aa,o));
    if(tid==0) r1[0]=aa;
  }
  __syncthreads();
  a=r1[0];
}

// exp(n * lw) with exact hi/lo argument split: expf(hi)*(1+lo)
__device__ __forceinline__ float exp_nlw(float n, float lw){
  float hi = __fmul_rn(n, lw);
  float lo = __fmaf_rn(n, lw, -hi);
  return __fmul_rn(expf(hi), __fadd_rn(1.f, lo));
}

__device__ __forceinline__ uint32_t smem_u32(const void* p){
  return (uint32_t)__cvta_generic_to_shared(p);
}

// ---------------- decay table builder (once; bit-exact vs in-kernel formulas) ----
__global__ void build_tables(const float* __restrict__ ld_in, const float* __restrict__ u_in){
  int h = blockIdx.x, tid = threadIdx.x;
  __shared__ float lws[Sq];
  if(tid<Sq){
    float w = expf(-expf(ld_in[h*Sq+tid]));
    float lw = logf(fmaxf(w,1e-38f));
    lws[tid]=lw;
    g_uex[h*Sq+tid]=expf(u_in[h*Sq+tid]);
    g_wCt[h*Sq+tid]=expf(__fmul_rn((float)Cq,lw));
  }
  __syncthreads();
  for(int idx=tid; idx<Cq*Sq; idx+=256){
    int t=idx>>6, s=idx&63;
    float lw=lws[s];
    g_ein[h*Cq*Sq+idx]=exp_nlw(-(float)t, lw);
    g_ekt[h*Cq*Sq+idx]=exp_nlw((float)t, lw);
    g_ek1[h*Cq*Sq+idx]=exp_nlw((float)(t+1), lw);
    g_ekc[h*Cq*Sq+idx]=exp_nlw((float)(Cq-1-t), lw);
  }
}

// ---------------- LN + abs-mean + bf16-int quantize (4 elems/thread) ----------------
__device__ __forceinline__ void ln_quant4(float4 v4, const float* gp, const float* bp,
                                          int j, int bt, float2* r1, float2* r2, int tid){
  float ps = ((v4.x+v4.y)+(v4.z+v4.w));
  float pq = ((__fmul_rn(v4.x,v4.x)+__fmul_rn(v4.y,v4.y))
             +(__fmul_rn(v4.z,v4.z)+__fmul_rn(v4.w,v4.w)));
  float2 s1=make_float2(ps,0.f), s2=make_float2(pq,0.f);
  block_sum2(s1,s2,r1,r2,tid);
  if(tid==0){
    float m0 = __fmul_rn(__fadd_rn(s1.x,s1.y), 1.f/Dq);
    double S1=(double)s1.x+(double)s1.y, S2=(double)s2.x+(double)s2.y;
    double var = S2*(1.0/Dq) - (double)m0*(2.0*S1*(1.0/Dq) - (double)m0);
    float inv0 = (float)(1.0/sqrt(var + 1e-5));
    r2[1]=make_float2(m0,inv0);
  }
  __syncthreads();
  float m=r2[1].x, inv=r2[1].y;
  int d0=tid<<2;
  float4 g4=*(const float4*)&gp[d0];
  float4 b4=*(const float4*)&bp[d0];
  float n0=__fadd_rn(__fmul_rn(__fmul_rn(__fsub_rn(v4.x,m),inv),g4.x),b4.x);
  float n1=__fadd_rn(__fmul_rn(__fmul_rn(__fsub_rn(v4.y,m),inv),g4.y),b4.y);
  float n2=__fadd_rn(__fmul_rn(__fmul_rn(__fsub_rn(v4.z,m),inv),g4.z),b4.z);
  float n3=__fadd_rn(__fmul_rn(__fmul_rn(__fsub_rn(v4.w,m),inv),g4.w),b4.w);
  float2 sa=make_float2(((fabsf(n0)+fabsf(n1))+(fabsf(n2)+fabsf(n3))),0.f);
  block_sum1(sa,r1,tid);
  float am = __fmul_rn(__fadd_rn(sa.x,sa.y), 1.f/Dq);
  float scale = __fdiv_rn(__fmul_rn(fmaxf(am,1e-8f),2.5f), 127.f);
  float q0=rintf(fminf(fmaxf(__fdiv_rn(n0,scale),-127.f),127.f));
  float q1=rintf(fminf(fmaxf(__fdiv_rn(n1,scale),-127.f),127.f));
  float q2=rintf(fminf(fmaxf(__fdiv_rn(n2,scale),-127.f),127.f));
  float q3=rintf(fminf(fmaxf(__fdiv_rn(n3,scale),-127.f),127.f));
  union { __nv_bfloat16 h[4]; uint2 u; } o;
  o.h[0]=__float2bfloat16_rn(q0); o.h[1]=__float2bfloat16_rn(q1);
  o.h[2]=__float2bfloat16_rn(q2); o.h[3]=__float2bfloat16_rn(q3);
  *(uint2*)&g_Xb[j][(size_t)bt*Dq + d0] = o.u;
  if(tid==0) g_xscale[j][bt]=scale;
}

// ---------------- weight quantization ----------------
__global__ void wq_part(const float* __restrict__ pw){
  int j=blockIdx.y, sl=blockIdx.x, tid=threadIdx.x;
  __shared__ float2 r1[8];
  const float* w = pw + j*(Dq*Dq) + sl*16384;
  float2 s=make_float2(0.f,0.f);
  for(int i=tid;i<16384;i+=256) df_acc(s,fabsf(w[i]));
  block_sum1(s,r1,tid);
  if(tid==0) g_wpart[j][sl]=__fadd_rn(s.x,s.y);
}
// fused: computes the global scale (identical fp64 reduction as the old wq_final)
// in thread 0 of each block, then quantizes. Redundant same-value g_wscale writes.
__global__ void wq_quant(const float* __restrict__ pw){
  __shared__ float sc_sh;
  int gi = blockIdx.x*1024 + threadIdx.x*4;
  int j  = gi >> 20;
  if(threadIdx.x==0){
    double s=0.0;
    for(int i=0;i<64;i++) s+=(double)g_wpart[j][i];
    float sc=fmaxf((float)(s*(1.0/(double)(Dq*Dq))),1e-8f);
    sc_sh=sc;
    g_wscale[j]=sc;
  }
  __syncthreads();
  float sc = sc_sh;
  float4 wv = *(const float4*)&pw[gi];
  union { __nv_bfloat16 h[4]; uint2 u; } o;
  o.h[0]=__float2bfloat16_rn(rintf(fminf(fmaxf(__fdiv_rn(wv.x,sc),-1.f),1.f)));
  o.h[1]=__float2bfloat16_rn(rintf(fminf(fmaxf(__fdiv_rn(wv.y,sc),-1.f),1.f)));
  o.h[2]=__float2bfloat16_rn(rintf(fminf(fmaxf(__fdiv_rn(wv.z,sc),-1.f),1.f)));
  o.h[3]=__float2bfloat16_rn(rintf(fminf(fmaxf(__fdiv_rn(wv.w,sc),-1.f),1.f)));
  *(uint2*)&(((__nv_bfloat16*)g_Wb)[gi]) = o.u;
}

// ---------------- token shift + LN + act quant (one block per (row, proj)) ----------------
__global__ void __launch_bounds__(256) prep_rkvg(
    const float* __restrict__ x,
    const float* __restrict__ mu_r, const float* __restrict__ mu_k,
    const float* __restrict__ mu_v, const float* __restrict__ mu_g,
    const float* __restrict__ ln_g, const float* __restrict__ ln_b){
  int bt=blockIdx.x, j=blockIdx.y;
  int t = bt & (Tq-1);
  int tid=threadIdx.x, d0=tid<<2;
  __shared__ float2 r1[8], r2[8];
  const float* mu = (j==0)?mu_r:(j==1)?mu_k:(j==2)?mu_v:mu_g;
  float4 xv = *(const float4*)&x[(size_t)bt*Dq + d0];
  float4 xp = (t==0)? make_float4(0.f,0.f,0.f,0.f)
                    : *(const float4*)&x[(size_t)(bt-1)*Dq + d0];
  float4 m4 = *(const float4*)&mu[d0];
  float4 v4;
  v4.x=__fadd_rn(xv.x,__fmul_rn(__fsub_rn(xp.x,xv.x),m4.x));
  v4.y=__fadd_rn(xv.y,__fmul_rn(__fsub_rn(xp.y,xv.y),m4.y));
  v4.z=__fadd_rn(xv.z,__fmul_rn(__fsub_rn(xp.z,xv.z),m4.z));
  v4.w=__fadd_rn(xv.w,__fmul_rn(__fsub_rn(xp.w,xv.w),m4.w));
  ln_quant4(v4, ln_g+j*Dq, ln_b+j*Dq, j, bt, r1, r2, tid);
}

// ---------------- HMMA bf16 GEMM: C[8192,1024] = Xb . Wb^T (exact int-in-bf16) ----------------
// CTA 128x128, warps 4(M)x2(N), warp tile 32x64, K staged 64 elems (128B), cp.async 2-buf.
// Single __syncthreads per k-iter; __launch_bounds__(256,2) for 2 CTAs/SM.
#define RSTRIDE 144   // 128B row + 16B pad: LDSM rows hit banks 4r..4r+3, conflict-free
__device__ __forceinline__ void mma_bf16(float* d, uint32_t a0,uint32_t a1,uint32_t a2,uint32_t a3,
                                         uint32_t b0,uint32_t b1){
  asm volatile("mma.sync.aligned.m16n8k16.row.col.f32.bf16.bf16.f32 "
    "{%0,%1,%2,%3}, {%4,%5,%6,%7}, {%8,%9}, {%0,%1,%2,%3};"
    : "+f"(d[0]),"+f"(d[1]),"+f"(d[2]),"+f"(d[3])
    : "r"(a0),"r"(a1),"r"(a2),"r"(a3),"r"(b0),"r"(b1));
}
__device__ __forceinline__ void ldsm4(uint32_t& r0,uint32_t& r1,uint32_t& r2,uint32_t& r3,
                                      uint32_t addr){
  asm volatile("ldmatrix.sync.aligned.m8n8.x4.shared.b16 {%0,%1,%2,%3}, [%4];"
    : "=r"(r0),"=r"(r1),"=r"(r2),"=r"(r3) : "r"(addr));
}
__device__ __forceinline__ void cp16(uint32_t daddr, const void* gptr){
  asm volatile("cp.async.cg.shared.global [%0], [%1], 16;" :: "r"(daddr), "l"(gptr));
}
__global__ void __launch_bounds__(256,2) gemm_hmma(int jbase, float* __restrict__ dout){
  extern __shared__ char sm8[];
  char* As = sm8;              // 2 bufs x 128 rows x RSTRIDE
  char* Bs = sm8 + 2*128*RSTRIDE;
  int j = jbase + blockIdx.z;
  const __nv_bfloat16* Ag = g_Xb[j];
  const __nv_bfloat16* Bg = g_Wb[j];
  float* C = (j==4)? dout : g_Y[j];
  int tid=threadIdx.x;
  int wid=tid>>5, lane=tid&31;
  int g=lane>>2, tig=lane&3;
  int wm=wid>>1, wn=wid&1;
  int m0=blockIdx.y*128, n0=blockIdx.x*128;
  int lrow=(lane&15), lhi=(lane>>4)*16;   // ldmatrix source row/col-byte split

  float acc[2][8][4];
  #pragma unroll
  for(int mi=0;mi<2;mi++)
    #pragma unroll
    for(int ni=0;ni<8;ni++)
      #pragma unroll
      for(int q=0;q<4;q++) acc[mi][ni][q]=0.f;

  int prow = tid>>1;                 // 2 threads per row; each copies 64B
  int poff = (tid&1)*64;
  const char* agp = (const char*)(Ag + (size_t)(m0+prow)*Dq) + poff;
  const char* bgp = (const char*)(Bg + (size_t)(n0+prow)*Dq) + poff;
  uint32_t asp = smem_u32(As + prow*RSTRIDE + poff);
  uint32_t bsp = smem_u32(Bs + prow*RSTRIDE + poff);
  const uint32_t bufstep = 128*RSTRIDE;

  // prologue: prefetch stage 0
  #pragma unroll
  for(int q=0;q<4;q++){ cp16(asp+q*16, agp+q*16); cp16(bsp+q*16, bgp+q*16); }
  asm volatile("cp.async.commit_group;");

  for(int kt=0;kt<16;kt++){
    int buf=kt&1;
    asm volatile("cp.async.wait_group 0;");
    __syncthreads();
    // prefetch kt+1 into buf^1: safe (sync above separates it from compute kt-1
    // which used buf^1), overlaps with compute of buf below.
    if(kt+1<16){
      int nb=buf^1;
      const char* a2p = agp + (kt+1)*128;
      const char* b2p = bgp + (kt+1)*128;
      uint32_t ad = asp + nb*bufstep;
      uint32_t bd = bsp + nb*bufstep;
      #pragma unroll
      for(int q=0;q<4;q++){ cp16(ad+q*16, a2p+q*16); cp16(bd+q*16, b2p+q*16); }
      asm volatile("cp.async.commit_group;");
    }
    const char* Ab = As + buf*bufstep;
    const char* Bb = Bs + buf*bufstep;
    #pragma unroll
    for(int s=0;s<4;s++){            // four k16 steps within the 64-elem slice
      uint32_t af[2][4];
      #pragma unroll
      for(int mi=0;mi<2;mi++){
        uint32_t ad = smem_u32(Ab + (wm*32+mi*16+lrow)*RSTRIDE + s*32 + lhi);
        ldsm4(af[mi][0],af[mi][1],af[mi][2],af[mi][3], ad);
      }
      uint32_t b0a[8], b1a[8];
      #pragma unroll
      for(int nb2=0;nb2<4;nb2++){
        uint32_t bd = smem_u32(Bb + (wn*64+nb2*16+lrow)*RSTRIDE + s*32 + lhi);
        uint32_t r0,r1,r2,r3;
        ldsm4(r0,r1,r2,r3, bd);
        b0a[2*nb2]=r0; b0a[2*nb2+1]=r1; b1a[2*nb2]=r2; b1a[2*nb2+1]=r3;
      }
      #pragma unroll
      for(int mi=0;mi<2;mi++)
        #pragma unroll
        for(int ni=0;ni<8;ni++)
          mma_bf16(acc[mi][ni], af[mi][0],af[mi][1],af[mi][2],af[mi][3],
                   b0a[ni], b1a[ni]);
    }
  }

  float ws=g_wscale[j];
  #pragma unroll
  for(int mi=0;mi<2;mi++){
    int r0 = m0 + wm*32 + mi*16 + g;
    float sc0=__fmul_rn(g_xscale[j][r0  ],ws);
    float sc1=__fmul_rn(g_xscale[j][r0+8],ws);
    #pragma unroll
    for(int ni=0;ni<8;ni++){
      int col = n0 + wn*64 + ni*8 + tig*2;
      float2 o0, o1;
      o0.x=__fmul_rn(acc[mi][ni][0],sc0);
      o0.y=__fmul_rn(acc[mi][ni][1],sc0);
      o1.x=__fmul_rn(acc[mi][ni][2],sc1);
      o1.y=__fmul_rn(acc[mi][ni][3],sc1);
      *(float2*)&C[(size_t)r0*Dq + col]     = o0;
      *(float2*)&C[(size_t)(r0+8)*Dq + col] = o1;
    }
  }
}

// ---------------- WKV phase A: per-chunk contribution G_c = (K .* w^{C-1-t})^T @ V ----------------
__global__ void wkv_contrib(){
  int c = blockIdx.x, bh = blockIdx.y;
  int b = bh>>4, h = bh&15;
  int tid = threadIdx.x;
  __shared__ float kw[Cq*Sq], vs[Cq*Sq];
  const float* Yk = g_Y[1];
  const float* Yv = g_Y[2];
  const float* ekc = g_ekc + h*Cq*Sq;
  int base = (b*Tq + c*Cq)*Dq + h*Sq;
  for(int idx=tid; idx<Cq*Sq; idx+=256){
    int t=idx>>6, s=idx&63;
    kw[idx] = __fmul_rn(Yk[base + t*Dq + s], ekc[idx]);
    vs[idx] = Yv[base + t*Dq + s];
  }
  __syncthreads();
  int ts=(tid>>4)*4, to=(tid&15)*4;
  float acc[4][4]={};
  for(int t=0;t<Cq;t++){
    float4 a=*(const float4*)&kw[t*Sq+ts];
    float4 v=*(const float4*)&vs[t*Sq+to];
    acc[0][0]+=a.x*v.x; acc[0][1]+=a.x*v.y; acc[0][2]+=a.x*v.z; acc[0][3]+=a.x*v.w;
    acc[1][0]+=a.y*v.x; acc[1][1]+=a.y*v.y; acc[1][2]+=a.y*v.z; acc[1][3]+=a.y*v.w;
    acc[2][0]+=a.z*v.x; acc[2][1]+=a.z*v.y; acc[2][2]+=a.z*v.z; acc[2][3]+=a.z*v.w;
    acc[3][0]+=a.w*v.x; acc[3][1]+=a.w*v.y; acc[3][2]+=a.w*v.z; acc[3][3]+=a.w*v.w;
  }
  float* G = &g_states[(bh*NCq + c)*Sq*Sq];
  #pragma unroll
  for(int i=0;i<4;i++)
    #pragma unroll
    for(int jj=0;jj<4;jj++)
      G[(ts+i)*Sq + to+jj]=acc[i][jj];
}

// ---------------- WKV phase B: scan ----------------
__global__ void wkv_scan(){
  int bh = blockIdx.x, h = bh&15;
  int tid = threadIdx.x;
  __shared__ float wC[Sq];
  if(tid<Sq) wC[tid]=g_wCt[h*Sq+tid];
  __syncthreads();
  for(int e=tid; e<Sq*Sq; e+=256){
    float wc = wC[e>>6];
    float cur = 0.f;
    float* Gp = &g_states[bh*NCq*Sq*Sq + e];
    for(int c=0;c<NCq;c++){
      float gv = Gp[c*Sq*Sq];
      Gp[c*Sq*Sq]=cur;
      cur = __fadd_rn(__fmul_rn(wc,cur), gv);
    }
  }
}

// ---------------- WKV phase C: per-chunk output ----------------
__global__ void __launch_bounds__(256) wkv_main(){
  extern __shared__ float sm[];
  float* rpT = sm;               // [S][C] : r * w^{-t}
  float* rwT = sm + 4096;        // [S][C] : r * w^{t+1}
  float* kpT = sm + 8192;        // [S][C] : k * w^{t}
  float* vs  = sm + 12288;       // [C][S]
  float* st  = sm + 16384;       // [S][S] state before chunk
  float* PT  = sm + 20480;       // [C(i)][C(t)] masked
  __shared__ float uex[Sq], dv[Cq];

  int c = blockIdx.x, bh = blockIdx.y;
  int b = bh>>4, h = bh&15;
  int tid = threadIdx.x;
  if(tid<Sq) uex[tid]=g_uex[h*Sq+tid];
  const float* Yr=g_Y[0]; const float* Yk=g_Y[1]; const float* Yv=g_Y[2];
  const float* ein = g_ein + h*Cq*Sq;
  const float* ekt = g_ekt + h*Cq*Sq;
  const float* ek1 = g_ek1 + h*Cq*Sq;
  int base = (b*Tq + c*Cq)*Dq + h*Sq;
  const float* Gst = &g_states[(bh*NCq + c)*Sq*Sq];
  for(int idx=tid; idx<Cq*Sq; idx+=256){
    int t=idx>>6, s=idx&63;
    float rv=Yr[base + t*Dq + s];
    float kv=Yk[base + t*Dq + s];
    float vv=Yv[base + t*Dq + s];
    rpT[s*Cq+t]=__fmul_rn(rv,ein[idx]);
    rwT[s*Cq+t]=__fmul_rn(rv,ek1[idx]);
    kpT[s*Cq+t]=__fmul_rn(kv,ekt[idx]);
    vs[t*Sq+s]=vv;
    st[idx]=Gst[idx];
  }
  __syncthreads();
  if(tid<Cq){
    float a=0.f;
    for(int s=0;s<Sq;s++) a += rpT[s*Cq+tid]*kpT[s*Cq+tid]*uex[s];
    dv[tid]=a;
  }
  __syncthreads();
  int tt=(tid>>4)*4, ti=(tid&15)*4;
  {
    float acc[4][4]={};
    for(int s=0;s<Sq;s++){
      float4 a=*(const float4*)&rpT[s*Cq+tt];
      float4 k4=*(const float4*)&kpT[s*Cq+ti];
      acc[0][0]+=a.x*k4.x; acc[0][1]+=a.x*k4.y; acc[0][2]+=a.x*k4.z; acc[0][3]+=a.x*k4.w;
      acc[1][0]+=a.y*k4.x; acc[1][1]+=a.y*k4.y; acc[1][2]+=a.y*k4.z; acc[1][3]+=a.y*k4.w;
      acc[2][0]+=a.z*k4.x; acc[2][1]+=a.z*k4.y; acc[2][2]+=a.z*k4.z; acc[2][3]+=a.z*k4.w;
      acc[3][0]+=a.w*k4.x; acc[3][1]+=a.w*k4.y; acc[3][2]+=a.w*k4.z; acc[3][3]+=a.w*k4.w;
    }
    #pragma unroll
    for(int i=0;i<4;i++)
      #pragma unroll
      for(int jj=0;jj<4;jj++)
        PT[(ti+jj)*Cq + (tt+i)] = (ti+jj >= tt+i) ? acc[i][jj] : 0.f;
  }
  __syncthreads();
  int to = ti;
  {
    float acc[4][4]={};
    for(int l=0;l<Sq;l++){
      float4 a =*(const float4*)&PT[l*Cq+tt];
      float4 v4=*(const float4*)&vs[l*Sq+to];
      float4 r4=*(const float4*)&rwT[l*Cq+tt];
      float4 s4=*(const float4*)&st[l*Sq+to];
      acc[0][0]+=a.x*v4.x+r4.x*s4.x; acc[0][1]+=a.x*v4.y+r4.x*s4.y;
      acc[0][2]+=a.x*v4.z+r4.x*s4.z; acc[0][3]+=a.x*v4.w+r4.x*s4.w;
      acc[1][0]+=a.y*v4.x+r4.y*s4.x; acc[1][1]+=a.y*v4.y+r4.y*s4.y;
      acc[1][2]+=a.y*v4.z+r4.y*s4.z; acc[1][3]+=a.y*v4.w+r4.y*s4.w;
      acc[2][0]+=a.z*v4.x+r4.z*s4.x; acc[2][1]+=a.z*v4.y+r4.z*s4.y;
      acc[2][2]+=a.z*v4.z+r4.z*s4.z; acc[2][3]+=a.z*v4.w+r4.z*s4.w;
      acc[3][0]+=a.w*v4.x+r4.w*s4.x; acc[3][1]+=a.w*v4.y+r4.w*s4.y;
      acc[3][2]+=a.w*v4.z+r4.w*s4.z; acc[3][3]+=a.w*v4.w+r4.w*s4.w;
    }
    #pragma unroll
    for(int i=0;i<4;i++){
      float dd = dv[tt+i];
      #pragma unroll
      for(int jj=0;jj<4;jj++){
        float y = __fadd_rn(acc[i][jj], __fmul_rn(dd,vs[(tt+i)*Sq + to+jj]));
        g_ywkv[(b*Tq + c*Cq + tt+i)*Dq + h*Sq + to+jj] = y;
      }
    }
  }
}

// ---------------- GroupNorm + SiLU gate + LN + quant ----------------
__global__ void __launch_bounds__(256) gate_prep(
    const float* __restrict__ gn_g, const float* __restrict__ gn_b,
    const float* __restrict__ ln_g, const float* __restrict__ ln_b){
  int bt=blockIdx.x, tid=threadIdx.x, d0=tid<<2;
  __shared__ float yr[Dq], gm[Hq], gi[Hq];
  __shared__ float2 r1[8], r2[8];
  float4 y4 = *(const float4*)&g_ywkv[(size_t)bt*Dq + d0];
  *(float4*)&yr[d0] = y4;
  __syncthreads();
  int w=tid>>5, lane=tid&31;
  for(int gg=2*w; gg<2*w+2; gg++){
    float e1=yr[gg*Sq+lane], e2=yr[gg*Sq+32+lane];
    float2 s = df_comb(make_float2(e1,0.f), make_float2(e2,0.f));
    #pragma unroll
    for(int o=16;o;o>>=1) s = df_comb(s, shfl2(s,o));
    float m=__fmul_rn(s.x+s.y, 1.f/Sq);
    float d1=__fsub_rn(e1,m), d2=__fsub_rn(e2,m);
    float2 s2 = df_comb(make_float2(__fmul_rn(d1,d1),0.f), make_float2(__fmul_rn(d2,d2),0.f));
    #pragma unroll
    for(int o=16;o;o>>=1) s2 = df_comb(s2, shfl2(s2,o));
    if(lane==0){
      gm[gg]=m;
      float ve=__fadd_rn(__fmul_rn(s2.x+s2.y, 1.f/Sq), 1e-5f);
      gi[gg]=(float)(1.0/sqrt((double)ve));
    }
  }
  __syncthreads();
  int gg=d0>>6;
  float4 gg4=*(const float4*)&gn_g[d0];
  float4 gb4=*(const float4*)&gn_b[d0];
  float4 gv4=*(const float4*)&g_Y[3][(size_t)bt*Dq + d0];
  float mm=gm[gg], ii=gi[gg];
  float4 v4;
  {
    float yn=__fadd_rn(__fmul_rn(__fmul_rn(__fsub_rn(y4.x,mm),ii),gg4.x),gb4.x);
    float sg=__fdiv_rn(1.f,__fadd_rn(1.f,expf(-gv4.x)));
    v4.x=__fmul_rn(yn,__fmul_rn(gv4.x,sg));
    yn=__fadd_rn(__fmul_rn(__fmul_rn(__fsub_rn(y4.y,mm),ii),gg4.y),gb4.y);
    sg=__fdiv_rn(1.f,__fadd_rn(1.f,expf(-gv4.y)));
    v4.y=__fmul_rn(yn,__fmul_rn(gv4.y,sg));
    yn=__fadd_rn(__fmul_rn(__fmul_rn(__fsub_rn(y4.z,mm),ii),gg4.z),gb4.z);
    sg=__fdiv_rn(1.f,__fadd_rn(1.f,expf(-gv4.z)));
    v4.z=__fmul_rn(yn,__fmul_rn(gv4.z,sg));
    yn=__fadd_rn(__fmul_rn(__fmul_rn(__fsub_rn(y4.w,mm),ii),gg4.w),gb4.w);
    sg=__fdiv_rn(1.f,__fadd_rn(1.f,expf(-gv4.w)));
    v4.w=__fmul_rn(yn,__fmul_rn(gv4.w,sg));
  }
  ln_quant4(v4, ln_g+4*Dq, ln_b+4*Dq, 4, bt, r1, r2, tid);
}

// ---------------- launch ----------------
extern "C" void kernel_launch(void* const* d_in, const int* in_sizes, int n_in,
                              void* d_out, int out_size){
  const float* x        =(const float*)d_in[0];
  const float* mu_r     =(const float*)d_in[1];
  const float* mu_k     =(const float*)d_in[2];
  const float* mu_v     =(const float*)d_in[3];
  const float* mu_g     =(const float*)d_in[4];
  const float* log_decay=(const float*)d_in[5];
  const float* u        =(const float*)d_in[6];
  const float* proj_w   =(const float*)d_in[7];
  const float* ln_g     =(const float*)d_in[8];
  const float* ln_b     =(const float*)d_in[9];
  const float* gn_g     =(const float*)d_in[10];
  const float* gn_b     =(const float*)d_in[11];
  float* out=(float*)d_out;

  cudaFuncSetAttribute(wkv_main,  cudaFuncAttributeMaxDynamicSharedMemorySize, 98304);
  cudaFuncSetAttribute(gemm_hmma, cudaFuncAttributeMaxDynamicSharedMemorySize, 4*128*RSTRIDE);

  // (0) weight abs-sum partials
  wq_part <<<dim3(64,5),256>>>(proj_w);
  // (1) token shift + LN + act quant for r,k,v,g
  prep_rkvg<<<dim3(NTq,4),256>>>(x,mu_r,mu_k,mu_v,mu_g,ln_g,ln_b);
  // (2) weight scale + quantize (fused)
  wq_quant<<<5120,256>>>(proj_w);
  // (3) 4 projection GEMMs, batched  <-- profiled launch index
  gemm_hmma<<<dim3(Dq/128, NTq/128, 4),256,4*128*RSTRIDE>>>(0,out);

  // decay/exp tables (needed from wkv_contrib onward)
  build_tables<<<Hq,256>>>(log_decay,u);

  // WKV
  wkv_contrib<<<dim3(NCq,BHq),256>>>();
  wkv_scan   <<<BHq,256>>>();
  wkv_main   <<<dim3(NCq,BHq),256,98304>>>();

  // GroupNorm + gate + final LN/quant
  gate_prep<<<NTq,256>>>(gn_g,gn_b,ln_g,ln_b);

  // output projection GEMM -> d_out
  gemm_hmma<<<dim3(Dq/128, NTq/128, 1),256,4*128*RSTRIDE>>>(4,out);
}

// round 10
// speedup vs baseline: 1.0004x; 1.0004x over previous
#include <cuda_runtime.h>
#include <cuda_bf16.h>
#include <stdint.h>

#define Bq 4
#define Tq 2048
#define Dq 1024
#define Hq 16
#define Sq 64
#define Cq 64
#define NTq (Bq*Tq)      // 8192 rows
#define NCq (Tq/Cq)      // 32 chunks
#define BHq (Bq*Hq)      // 64 (b,h) pairs

// ---------------- scratch (static __device__, allocation-free) ----------------
__device__ __nv_bfloat16 g_Wb[5][Dq*Dq];   // ternary weights as bf16 (-1,0,1)
__device__ float  g_wpart[5][64];
__device__ float  g_wscale[5];
__device__ __nv_bfloat16 g_Xb[5][NTq*Dq];  // quantized activations as bf16 ints
__device__ float  g_xscale[5][NTq];
__device__ float  g_Y[4][NTq*Dq];          // r,k,v,g projection outputs (fp32)
__device__ float  g_states[BHq*NCq*Sq*Sq]; // per-chunk contributions -> states
__device__ float  g_ywkv[NTq*Dq];          // wkv output in (B,T,D)
// decay tables: [h][t][s], bit-exact replicas of the per-block exp computations
__device__ float  g_ein[Hq*Cq*Sq];         // exp(-t*lw)
__device__ float  g_ekt[Hq*Cq*Sq];         // exp(t*lw)
__device__ float  g_ek1[Hq*Cq*Sq];         // exp((t+1)*lw)
__device__ float  g_ekc[Hq*Cq*Sq];         // exp((C-1-t)*lw)
__device__ float  g_uex[Hq*Sq];            // exp(u)
__device__ float  g_wCt[Hq*Sq];            // exp(C*lw)

// ---------------- compensated-sum helpers ----------------
__device__ __forceinline__ float2 df_comb(float2 a, float2 b){
  float s  = a.x + b.x;
  float bp = s - a.x;
  float er = (a.x - (s - bp)) + (b.x - bp);
  return make_float2(s, a.y + b.y + er);
}
__device__ __forceinline__ void df_acc(float2& s, float v){
  float t=s.x+v; float bp=t-s.x; float er=(s.x-(t-bp))+(v-bp);
  s.x=t; s.y+=er;
}
__device__ __forceinline__ float2 shfl2(float2 v, int o){
  return make_float2(__shfl_xor_sync(0xffffffffu,v.x,o),
                     __shfl_xor_sync(0xffffffffu,v.y,o));
}
// 3-sync block reductions over 256 threads (8 warps)
__device__ __forceinline__ void block_sum2(float2& a, float2& b, float2* r1, float2* r2, int tid){
  #pragma unroll
  for(int o=16;o;o>>=1){ a=df_comb(a,shfl2(a,o)); b=df_comb(b,shfl2(b,o)); }
  __syncthreads();
  if((tid&31)==0){ r1[tid>>5]=a; r2[tid>>5]=b; }
  __syncthreads();
  if(tid<32){
    float2 aa=(tid<8)?r1[tid]:make_float2(0.f,0.f);
    float2 bb=(tid<8)?r2[tid]:make_float2(0.f,0.f);
    #pragma unroll
    for(int o=4;o;o>>=1){ aa=df_comb(aa,shfl2(aa,o)); bb=df_comb(bb,shfl2(bb,o)); }
    if(tid==0){ r1[0]=aa; r2[0]=bb; }
  }
  __syncthreads();
  a=r1[0]; b=r2[0];
}
__device__ __forceinline__ void block_sum1(float2& a, float2* r1, int tid){
  #pragma unroll
  for(int o=16;o;o>>=1) a=df_comb(a,shfl2(a,o));
  __syncthreads();
  if((tid&31)==0) r1[tid>>5]=a;
  __syncthreads();
  if(tid<32){
    float2 aa=(tid<8)?r1[tid]:make_float2(0.f,0.f);
    #pragma unroll
    for(int o=4;o;o>>=1) aa=df_comb(aa,shfl2(aa,o));
    if(tid==0) r1[0]=aa;
  }
  __syncthreads();
  a=r1[0];
}

// exp(n * lw) with exact hi/lo argument split: expf(hi)*(1+lo)
__device__ __forceinline__ float exp_nlw(float n, float lw){
  float hi = __fmul_rn(n, lw);
  float lo = __fmaf_rn(n, lw, -hi);
  return __fmul_rn(expf(hi), __fadd_rn(1.f, lo));
}

__device__ __forceinline__ uint32_t smem_u32(const void* p){
  return (uint32_t)__cvta_generic_to_shared(p);
}

// ---------------- decay table builder (once; bit-exact vs in-kernel formulas) ----
__global__ void build_tables(const float* __restrict__ ld_in, const float* __restrict__ u_in){
  int h = blockIdx.x, tid = threadIdx.x;
  __shared__ float lws[Sq];
  if(tid<Sq){
    float w = expf(-expf(ld_in[h*Sq+tid]));
    float lw = logf(fmaxf(w,1e-38f));
    lws[tid]=lw;
    g_uex[h*Sq+tid]=expf(u_in[h*Sq+tid]);
    g_wCt[h*Sq+tid]=expf(__fmul_rn((float)Cq,lw));
  }
  __syncthreads();
  for(int idx=tid; idx<Cq*Sq; idx+=256){
    int t=idx>>6, s=idx&63;
    float lw=lws[s];
    g_ein[h*Cq*Sq+idx]=exp_nlw(-(float)t, lw);
    g_ekt[h*Cq*Sq+idx]=exp_nlw((float)t, lw);
    g_ek1[h*Cq*Sq+idx]=exp_nlw((float)(t+1), lw);
    g_ekc[h*Cq*Sq+idx]=exp_nlw((float)(Cq-1-t), lw);
  }
}

// ---------------- LN + abs-mean + bf16-int quantize (4 elems/thread) ----------------
__device__ __forceinline__ void ln_quant4(float4 v4, const float* gp, const float* bp,
                                          int j, int bt, float2* r1, float2* r2, int tid){
  float ps = ((v4.x+v4.y)+(v4.z+v4.w));
  float pq = ((__fmul_rn(v4.x,v4.x)+__fmul_rn(v4.y,v4.y))
             +(__fmul_rn(v4.z,v4.z)+__fmul_rn(v4.w,v4.w)));
  float2 s1=make_float2(ps,0.f), s2=make_float2(pq,0.f);
  block_sum2(s1,s2,r1,r2,tid);
  if(tid==0){
    float m0 = __fmul_rn(__fadd_rn(s1.x,s1.y), 1.f/Dq);
    double S1=(double)s1.x+(double)s1.y, S2=(double)s2.x+(double)s2.y;
    double var = S2*(1.0/Dq) - (double)m0*(2.0*S1*(1.0/Dq) - (double)m0);
    float inv0 = (float)(1.0/sqrt(var + 1e-5));
    r2[1]=make_float2(m0,inv0);
  }
  __syncthreads();
  float m=r2[1].x, inv=r2[1].y;
  int d0=tid<<2;
  float4 g4=*(const float4*)&gp[d0];
  float4 b4=*(const float4*)&bp[d0];
  float n0=__fadd_rn(__fmul_rn(__fmul_rn(__fsub_rn(v4.x,m),inv),g4.x),b4.x);
  float n1=__fadd_rn(__fmul_rn(__fmul_rn(__fsub_rn(v4.y,m),inv),g4.y),b4.y);
  float n2=__fadd_rn(__fmul_rn(__fmul_rn(__fsub_rn(v4.z,m),inv),g4.z),b4.z);
  float n3=__fadd_rn(__fmul_rn(__fmul_rn(__fsub_rn(v4.w,m),inv),g4.w),b4.w);
  float2 sa=make_float2(((fabsf(n0)+fabsf(n1))+(fabsf(n2)+fabsf(n3))),0.f);
  block_sum1(sa,r1,tid);
  float am = __fmul_rn(__fadd_rn(sa.x,sa.y), 1.f/Dq);
  float scale = __fdiv_rn(__fmul_rn(fmaxf(am,1e-8f),2.5f), 127.f);
  float q0=rintf(fminf(fmaxf(__fdiv_rn(n0,scale),-127.f),127.f));
  float q1=rintf(fminf(fmaxf(__fdiv_rn(n1,scale),-127.f),127.f));
  float q2=rintf(fminf(fmaxf(__fdiv_rn(n2,scale),-127.f),127.f));
  float q3=rintf(fminf(fmaxf(__fdiv_rn(n3,scale),-127.f),127.f));
  union { __nv_bfloat16 h[4]; uint2 u; } o;
  o.h[0]=__float2bfloat16_rn(q0); o.h[1]=__float2bfloat16_rn(q1);
  o.h[2]=__float2bfloat16_rn(q2); o.h[3]=__float2bfloat16_rn(q3);
  *(uint2*)&g_Xb[j][(size_t)bt*Dq + d0] = o.u;
  if(tid==0) g_xscale[j][bt]=scale;
}

// ---------------- weight quantization ----------------
__global__ void wq_part(const float* __restrict__ pw){
  int j=blockIdx.y, sl=blockIdx.x, tid=threadIdx.x;
  __shared__ float2 r1[8];
  const float* w = pw + j*(Dq*Dq) + sl*16384;
  float2 s=make_float2(0.f,0.f);
  for(int i=tid;i<16384;i+=256) df_acc(s,fabsf(w[i]));
  block_sum1(s,r1,tid);
  if(tid==0) g_wpart[j][sl]=__fadd_rn(s.x,s.y);
}
// fused: computes the global scale (identical fp64 reduction as the old wq_final)
// in thread 0 of each block, then quantizes. Redundant same-value g_wscale writes.
__global__ void wq_quant(const float* __restrict__ pw){
  __shared__ float sc_sh;
  int gi = blockIdx.x*1024 + threadIdx.x*4;
  int j  = gi >> 20;
  if(threadIdx.x==0){
    double s=0.0;
    for(int i=0;i<64;i++) s+=(double)g_wpart[j][i];
    float sc=fmaxf((float)(s*(1.0/(double)(Dq*Dq))),1e-8f);
    sc_sh=sc;
    g_wscale[j]=sc;
  }
  __syncthreads();
  float sc = sc_sh;
  float4 wv = *(const float4*)&pw[gi];
  union { __nv_bfloat16 h[4]; uint2 u; } o;
  o.h[0]=__float2bfloat16_rn(rintf(fminf(fmaxf(__fdiv_rn(wv.x,sc),-1.f),1.f)));
  o.h[1]=__float2bfloat16_rn(rintf(fminf(fmaxf(__fdiv_rn(wv.y,sc),-1.f),1.f)));
  o.h[2]=__float2bfloat16_rn(rintf(fminf(fmaxf(__fdiv_rn(wv.z,sc),-1.f),1.f)));
  o.h[3]=__float2bfloat16_rn(rintf(fminf(fmaxf(__fdiv_rn(wv.w,sc),-1.f),1.f)));
  *(uint2*)&(((__nv_bfloat16*)g_Wb)[gi]) = o.u;
}

// ---------------- token shift + LN + act quant (one block per (row, proj)) ----------------
__global__ void __launch_bounds__(256) prep_rkvg(
    const float* __restrict__ x,
    const float* __restrict__ mu_r, const float* __restrict__ mu_k,
    const float* __restrict__ mu_v, const float* __restrict__ mu_g,
    const float* __restrict__ ln_g, const float* __restrict__ ln_b){
  int bt=blockIdx.x, j=blockIdx.y;
  int t = bt & (Tq-1);
  int tid=threadIdx.x, d0=tid<<2;
  __shared__ float2 r1[8], r2[8];
  const float* mu = (j==0)?mu_r:(j==1)?mu_k:(j==2)?mu_v:mu_g;
  float4 xv = *(const float4*)&x[(size_t)bt*Dq + d0];
  float4 xp = (t==0)? make_float4(0.f,0.f,0.f,0.f)
                    : *(const float4*)&x[(size_t)(bt-1)*Dq + d0];
  float4 m4 = *(const float4*)&mu[d0];
  float4 v4;
  v4.x=__fadd_rn(xv.x,__fmul_rn(__fsub_rn(xp.x,xv.x),m4.x));
  v4.y=__fadd_rn(xv.y,__fmul_rn(__fsub_rn(xp.y,xv.y),m4.y));
  v4.z=__fadd_rn(xv.z,__fmul_rn(__fsub_rn(xp.z,xv.z),m4.z));
  v4.w=__fadd_rn(xv.w,__fmul_rn(__fsub_rn(xp.w,xv.w),m4.w));
  ln_quant4(v4, ln_g+j*Dq, ln_b+j*Dq, j, bt, r1, r2, tid);
}

// ---------------- HMMA bf16 GEMM: C[8192,1024] = Xb . Wb^T (exact int-in-bf16) ----------------
// CTA 128x128, warps 4(M)x2(N), warp tile 32x64, K staged 64 elems (128B),
// THREE-stage circular cp.async pipeline (wait_group 1 steady-state).
#define RSTRIDE 144   // 128B row + 16B pad: LDSM rows hit banks 4r..4r+3, conflict-free
#define STAGEB  (256*RSTRIDE)   // one stage: 128 A-rows + 128 B-rows
__device__ __forceinline__ void mma_bf16(float* d, uint32_t a0,uint32_t a1,uint32_t a2,uint32_t a3,
                                         uint32_t b0,uint32_t b1){
  asm volatile("mma.sync.aligned.m16n8k16.row.col.f32.bf16.bf16.f32 "
    "{%0,%1,%2,%3}, {%4,%5,%6,%7}, {%8,%9}, {%0,%1,%2,%3};"
    : "+f"(d[0]),"+f"(d[1]),"+f"(d[2]),"+f"(d[3])
    : "r"(a0),"r"(a1),"r"(a2),"r"(a3),"r"(b0),"r"(b1));
}
__device__ __forceinline__ void ldsm4(uint32_t& r0,uint32_t& r1,uint32_t& r2,uint32_t& r3,
                                      uint32_t addr){
  asm volatile("ldmatrix.sync.aligned.m8n8.x4.shared.b16 {%0,%1,%2,%3}, [%4];"
    : "=r"(r0),"=r"(r1),"=r"(r2),"=r"(r3) : "r"(addr));
}
__device__ __forceinline__ void cp16(uint32_t daddr, const void* gptr){
  asm volatile("cp.async.cg.shared.global [%0], [%1], 16;" :: "r"(daddr), "l"(gptr));
}
__global__ void __launch_bounds__(256,2) gemm_hmma(int jbase, float* __restrict__ dout){
  extern __shared__ char sm8[];
  int j = jbase + blockIdx.z;
  const __nv_bfloat16* Ag = g_Xb[j];
  const __nv_bfloat16* Bg = g_Wb[j];
  float* C = (j==4)? dout : g_Y[j];
  int tid=threadIdx.x;
  int wid=tid>>5, lane=tid&31;
  int g=lane>>2, tig=lane&3;
  int wm=wid>>1, wn=wid&1;
  int m0=blockIdx.y*128, n0=blockIdx.x*128;
  int lrow=(lane&15), lhi=(lane>>4)*16;   // ldmatrix source row/col-byte split

  float acc[2][8][4];
  #pragma unroll
  for(int mi=0;mi<2;mi++)
    #pragma unroll
    for(int ni=0;ni<8;ni++)
      #pragma unroll
      for(int q=0;q<4;q++) acc[mi][ni][q]=0.f;

  int prow = tid>>1;                 // 2 threads per row; each copies 64B
  int poff = (tid&1)*64;
  const char* agp = (const char*)(Ag + (size_t)(m0+prow)*Dq) + poff;
  const char* bgp = (const char*)(Bg + (size_t)(n0+prow)*Dq) + poff;
  // within a stage: A rows at [0,128*RSTRIDE), B rows at [128*RSTRIDE, 256*RSTRIDE)
  uint32_t asp = smem_u32(sm8 + prow*RSTRIDE + poff);
  uint32_t bsp = asp + 128*RSTRIDE;

  // prologue: prefetch stages 0 and 1 (two committed groups)
  #pragma unroll
  for(int st=0; st<2; st++){
    uint32_t ad = asp + st*STAGEB, bd = bsp + st*STAGEB;
    const char* a2p = agp + st*128;
    const char* b2p = bgp + st*128;
    #pragma unroll
    for(int q=0;q<4;q++){ cp16(ad+q*16, a2p+q*16); cp16(bd+q*16, b2p+q*16); }
    asm volatile("cp.async.commit_group;");
  }

  int stage = 0;
  for(int kt=0;kt<16;kt++){
    if(kt<14) asm volatile("cp.async.wait_group 1;");
    else      asm volatile("cp.async.wait_group 0;");
    __syncthreads();   // also protects stage (kt+2)%3, last read at iter kt-1
    if(kt+2<16){
      int ps = stage+2; if(ps>=3) ps-=3;
      uint32_t ad = asp + ps*STAGEB, bd = bsp + ps*STAGEB;
      const char* a2p = agp + (kt+2)*128;
      const char* b2p = bgp + (kt+2)*128;
      #pragma unroll
      for(int q=0;q<4;q++){ cp16(ad+q*16, a2p+q*16); cp16(bd+q*16, b2p+q*16); }
      asm volatile("cp.async.commit_group;");
    }
    const char* Ab = sm8 + stage*STAGEB;
    const char* Bb = Ab + 128*RSTRIDE;
    #pragma unroll
    for(int s=0;s<4;s++){            // four k16 steps within the 64-elem slice
      uint32_t af[2][4];
      #pragma unroll
      for(int mi=0;mi<2;mi++){
        uint32_t ad = smem_u32(Ab + (wm*32+mi*16+lrow)*RSTRIDE + s*32 + lhi);
        ldsm4(af[mi][0],af[mi][1],af[mi][2],af[mi][3], ad);
      }
      uint32_t b0a[8], b1a[8];
      #pragma unroll
      for(int nb2=0;nb2<4;nb2++){
        uint32_t bd = smem_u32(Bb + (wn*64+nb2*16+lrow)*RSTRIDE + s*32 + lhi);
        uint32_t r0,r1,r2,r3;
        ldsm4(r0,r1,r2,r3, bd);
        b0a[2*nb2]=r0; b0a[2*nb2+1]=r1; b1a[2*nb2]=r2; b1a[2*nb2+1]=r3;
      }
      #pragma unroll
      for(int mi=0;mi<2;mi++)
        #pragma unroll
        for(int ni=0;ni<8;ni++)
          mma_bf16(acc[mi][ni], af[mi][0],af[mi][1],af[mi][2],af[mi][3],
                   b0a[ni], b1a[ni]);
    }
    stage++; if(stage>=3) stage=0;
  }

  float ws=g_wscale[j];
  #pragma unroll
  for(int mi=0;mi<2;mi++){
    int r0 = m0 + wm*32 + mi*16 + g;
    float sc0=__fmul_rn(g_xscale[j][r0  ],ws);
    float sc1=__fmul_rn(g_xscale[j][r0+8],ws);
    #pragma unroll
    for(int ni=0;ni<8;ni++){
      int col = n0 + wn*64 + ni*8 + tig*2;
      float2 o0, o1;
      o0.x=__fmul_rn(acc[mi][ni][0],sc0);
      o0.y=__fmul_rn(acc[mi][ni][1],sc0);
      o1.x=__fmul_rn(acc[mi][ni][2],sc1);
      o1.y=__fmul_rn(acc[mi][ni][3],sc1);
      *(float2*)&C[(size_t)r0*Dq + col]     = o0;
      *(float2*)&C[(size_t)(r0+8)*Dq + col] = o1;
    }
  }
}

// ---------------- WKV phase A: per-chunk contribution G_c = (K .* w^{C-1-t})^T @ V ----------------
__global__ void wkv_contrib(){
  int c = blockIdx.x, bh = blockIdx.y;
  int b = bh>>4, h = bh&15;
  int tid = threadIdx.x;
  __shared__ float kw[Cq*Sq], vs[Cq*Sq];
  const float* Yk = g_Y[1];
  const float* Yv = g_Y[2];
  const float* ekc = g_ekc + h*Cq*Sq;
  int base = (b*Tq + c*Cq)*Dq + h*Sq;
  for(int idx=tid; idx<Cq*Sq; idx+=256){
    int t=idx>>6, s=idx&63;
    kw[idx] = __fmul_rn(Yk[base + t*Dq + s], ekc[idx]);
    vs[idx] = Yv[base + t*Dq + s];
  }
  __syncthreads();
  int ts=(tid>>4)*4, to=(tid&15)*4;
  float acc[4][4]={};
  for(int t=0;t<Cq;t++){
    float4 a=*(const float4*)&kw[t*Sq+ts];
    float4 v=*(const float4*)&vs[t*Sq+to];
    acc[0][0]+=a.x*v.x; acc[0][1]+=a.x*v.y; acc[0][2]+=a.x*v.z; acc[0][3]+=a.x*v.w;
    acc[1][0]+=a.y*v.x; acc[1][1]+=a.y*v.y; acc[1][2]+=a.y*v.z; acc[1][3]+=a.y*v.w;
    acc[2][0]+=a.z*v.x; acc[2][1]+=a.z*v.y; acc[2][2]+=a.z*v.z; acc[2][3]+=a.z*v.w;
    acc[3][0]+=a.w*v.x; acc[3][1]+=a.w*v.y; acc[3][2]+=a.w*v.z; acc[3][3]+=a.w*v.w;
  }
  float* G = &g_states[(bh*NCq + c)*Sq*Sq];
  #pragma unroll
  for(int i=0;i<4;i++)
    #pragma unroll
    for(int jj=0;jj<4;jj++)
      G[(ts+i)*Sq + to+jj]=acc[i][jj];
}

// ---------------- WKV phase B: scan ----------------
__global__ void wkv_scan(){
  int bh = blockIdx.x, h = bh&15;
  int tid = threadIdx.x;
  __shared__ float wC[Sq];
  if(tid<Sq) wC[tid]=g_wCt[h*Sq+tid];
  __syncthreads();
  for(int e=tid; e<Sq*Sq; e+=256){
    float wc = wC[e>>6];
    float cur = 0.f;
    float* Gp = &g_states[bh*NCq*Sq*Sq + e];
    for(int c=0;c<NCq;c++){
      float gv = Gp[c*Sq*Sq];
      Gp[c*Sq*Sq]=cur;
      cur = __fadd_rn(__fmul_rn(wc,cur), gv);
    }
  }
}

// ---------------- WKV phase C: per-chunk output ----------------
__global__ void __launch_bounds__(256) wkv_main(){
  extern __shared__ float sm[];
  float* rpT = sm;               // [S][C] : r * w^{-t}
  float* rwT = sm + 4096;        // [S][C] : r * w^{t+1}
  float* kpT = sm + 8192;        // [S][C] : k * w^{t}
  float* vs  = sm + 12288;       // [C][S]
  float* st  = sm + 16384;       // [S][S] state before chunk
  float* PT  = sm + 20480;       // [C(i)][C(t)] masked
  __shared__ float uex[Sq], dv[Cq];

  int c = blockIdx.x, bh = blockIdx.y;
  int b = bh>>4, h = bh&15;
  int tid = threadIdx.x;
  if(tid<Sq) uex[tid]=g_uex[h*Sq+tid];
  const float* Yr=g_Y[0]; const float* Yk=g_Y[1]; const float* Yv=g_Y[2];
  const float* ein = g_ein + h*Cq*Sq;
  const float* ekt = g_ekt + h*Cq*Sq;
  const float* ek1 = g_ek1 + h*Cq*Sq;
  int base = (b*Tq + c*Cq)*Dq + h*Sq;
  const float* Gst = &g_states[(bh*NCq + c)*Sq*Sq];
  for(int idx=tid; idx<Cq*Sq; idx+=256){
    int t=idx>>6, s=idx&63;
    float rv=Yr[base + t*Dq + s];
    float kv=Yk[base + t*Dq + s];
    float vv=Yv[base + t*Dq + s];
    rpT[s*Cq+t]=__fmul_rn(rv,ein[idx]);
    rwT[s*Cq+t]=__fmul_rn(rv,ek1[idx]);
    kpT[s*Cq+t]=__fmul_rn(kv,ekt[idx]);
    vs[t*Sq+s]=vv;
    st[idx]=Gst[idx];
  }
  __syncthreads();
  if(tid<Cq){
    float a=0.f;
    for(int s=0;s<Sq;s++) a += rpT[s*Cq+tid]*kpT[s*Cq+tid]*uex[s];
    dv[tid]=a;
  }
  __syncthreads();
  int tt=(tid>>4)*4, ti=(tid&15)*4;
  {
    float acc[4][4]={};
    for(int s=0;s<Sq;s++){
      float4 a=*(const float4*)&rpT[s*Cq+tt];
      float4 k4=*(const float4*)&kpT[s*Cq+ti];
      acc[0][0]+=a.x*k4.x; acc[0][1]+=a.x*k4.y; acc[0][2]+=a.x*k4.z; acc[0][3]+=a.x*k4.w;
      acc[1][0]+=a.y*k4.x; acc[1][1]+=a.y*k4.y; acc[1][2]+=a.y*k4.z; acc[1][3]+=a.y*k4.w;
      acc[2][0]+=a.z*k4.x; acc[2][1]+=a.z*k4.y; acc[2][2]+=a.z*k4.z; acc[2][3]+=a.z*k4.w;
      acc[3][0]+=a.w*k4.x; acc[3][1]+=a.w*k4.y; acc[3][2]+=a.w*k4.z; acc[3][3]+=a.w*k4.w;
    }
    #pragma unroll
    for(int i=0;i<4;i++)
      #pragma unroll
      for(int jj=0;jj<4;jj++)
        PT[(ti+jj)*Cq + (tt+i)] = (ti+jj >= tt+i) ? acc[i][jj] : 0.f;
  }
  __syncthreads();
  int to = ti;
  {
    float acc[4][4]={};
    for(int l=0;l<Sq;l++){
      float4 a =*(const float4*)&PT[l*Cq+tt];
      float4 v4=*(const float4*)&vs[l*Sq+to];
      float4 r4=*(const float4*)&rwT[l*Cq+tt];
      float4 s4=*(const float4*)&st[l*Sq+to];
      acc[0][0]+=a.x*v4.x+r4.x*s4.x; acc[0][1]+=a.x*v4.y+r4.x*s4.y;
      acc[0][2]+=a.x*v4.z+r4.x*s4.z; acc[0][3]+=a.x*v4.w+r4.x*s4.w;
      acc[1][0]+=a.y*v4.x+r4.y*s4.x; acc[1][1]+=a.y*v4.y+r4.y*s4.y;
      acc[1][2]+=a.y*v4.z+r4.y*s4.z; acc[1][3]+=a.y*v4.w+r4.y*s4.w;
      acc[2][0]+=a.z*v4.x+r4.z*s4.x; acc[2][1]+=a.z*v4.y+r4.z*s4.y;
      acc[2][2]+=a.z*v4.z+r4.z*s4.z; acc[2][3]+=a.z*v4.w+r4.z*s4.w;
      acc[3][0]+=a.w*v4.x+r4.w*s4.x; acc[3][1]+=a.w*v4.y+r4.w*s4.y;
      acc[3][2]+=a.w*v4.z+r4.w*s4.z; acc[3][3]+=a.w*v4.w+r4.w*s4.w;
    }
    #pragma unroll
    for(int i=0;i<4;i++){
      float dd = dv[tt+i];
      #pragma unroll
      for(int jj=0;jj<4;jj++){
        float y = __fadd_rn(acc[i][jj], __fmul_rn(dd,vs[(tt+i)*Sq + to+jj]));
        g_ywkv[(b*Tq + c*Cq + tt+i)*Dq + h*Sq + to+jj] = y;
      }
    }
  }
}

// ---------------- GroupNorm + SiLU gate + LN + quant ----------------
__global__ void __launch_bounds__(256) gate_prep(
    const float* __restrict__ gn_g, const float* __restrict__ gn_b,
    const float* __restrict__ ln_g, const float* __restrict__ ln_b){
  int bt=blockIdx.x, tid=threadIdx.x, d0=tid<<2;
  __shared__ float yr[Dq], gm[Hq], gi[Hq];
  __shared__ float2 r1[8], r2[8];
  float4 y4 = *(const float4*)&g_ywkv[(size_t)bt*Dq + d0];
  *(float4*)&yr[d0] = y4;
  __syncthreads();
  int w=tid>>5, lane=tid&31;
  for(int gg=2*w; gg<2*w+2; gg++){
    float e1=yr[gg*Sq+lane], e2=yr[gg*Sq+32+lane];
    float2 s = df_comb(make_float2(e1,0.f), make_float2(e2,0.f));
    #pragma unroll
    for(int o=16;o;o>>=1) s = df_comb(s, shfl2(s,o));
    float m=__fmul_rn(s.x+s.y, 1.f/Sq);
    float d1=__fsub_rn(e1,m), d2=__fsub_rn(e2,m);
    float2 s2 = df_comb(make_float2(__fmul_rn(d1,d1),0.f), make_float2(__fmul_rn(d2,d2),0.f));
    #pragma unroll
    for(int o=16;o;o>>=1) s2 = df_comb(s2, shfl2(s2,o));
    if(lane==0){
      gm[gg]=m;
      float ve=__fadd_rn(__fmul_rn(s2.x+s2.y, 1.f/Sq), 1e-5f);
      gi[gg]=(float)(1.0/sqrt((double)ve));
    }
  }
  __syncthreads();
  int gg=d0>>6;
  float4 gg4=*(const float4*)&gn_g[d0];
  float4 gb4=*(const float4*)&gn_b[d0];
  float4 gv4=*(const float4*)&g_Y[3][(size_t)bt*Dq + d0];
  float mm=gm[gg], ii=gi[gg];
  float4 v4;
  {
    float yn=__fadd_rn(__fmul_rn(__fmul_rn(__fsub_rn(y4.x,mm),ii),gg4.x),gb4.x);
    float sg=__fdiv_rn(1.f,__fadd_rn(1.f,expf(-gv4.x)));
    v4.x=__fmul_rn(yn,__fmul_rn(gv4.x,sg));
    yn=__fadd_rn(__fmul_rn(__fmul_rn(__fsub_rn(y4.y,mm),ii),gg4.y),gb4.y);
    sg=__fdiv_rn(1.f,__fadd_rn(1.f,expf(-gv4.y)));
    v4.y=__fmul_rn(yn,__fmul_rn(gv4.y,sg));
    yn=__fadd_rn(__fmul_rn(__fmul_rn(__fsub_rn(y4.z,mm),ii),gg4.z),gb4.z);
    sg=__fdiv_rn(1.f,__fadd_rn(1.f,expf(-gv4.z)));
    v4.z=__fmul_rn(yn,__fmul_rn(gv4.z,sg));
    yn=__fadd_rn(__fmul_rn(__fmul_rn(__fsub_rn(y4.w,mm),ii),gg4.w),gb4.w);
    sg=__fdiv_rn(1.f,__fadd_rn(1.f,expf(-gv4.w)));
    v4.w=__fmul_rn(yn,__fmul_rn(gv4.w,sg));
  }
  ln_quant4(v4, ln_g+4*Dq, ln_b+4*Dq, 4, bt, r1, r2, tid);
}

// ---------------- launch ----------------
extern "C" void kernel_launch(void* const* d_in, const int* in_sizes, int n_in,
                              void* d_out, int out_size){
  const float* x        =(const float*)d_in[0];
  const float* mu_r     =(const float*)d_in[1];
  const float* mu_k     =(const float*)d_in[2];
  const float* mu_v     =(const float*)d_in[3];
  const float* mu_g     =(const float*)d_in[4];
  const float* log_decay=(const float*)d_in[5];
  const float* u        =(const float*)d_in[6];
  const float* proj_w   =(const float*)d_in[7];
  const float* ln_g     =(const float*)d_in[8];
  const float* ln_b     =(const float*)d_in[9];
  const float* gn_g     =(const float*)d_in[10];
  const float* gn_b     =(const float*)d_in[11];
  float* out=(float*)d_out;

  cudaFuncSetAttribute(wkv_main,  cudaFuncAttributeMaxDynamicSharedMemorySize, 98304);
  cudaFuncSetAttribute(gemm_hmma, cudaFuncAttributeMaxDynamicSharedMemorySize, 3*STAGEB);

  // (0) weight abs-sum partials
  wq_part <<<dim3(64,5),256>>>(proj_w);
  // (1) token shift + LN + act quant for r,k,v,g
  prep_rkvg<<<dim3(NTq,4),256>>>(x,mu_r,mu_k,mu_v,mu_g,ln_g,ln_b);
  // (2) weight scale + quantize (fused)
  wq_quant<<<5120,256>>>(proj_w);
  // (3) 4 projection GEMMs, batched  <-- profiled launch index
  gemm_hmma<<<dim3(Dq/128, NTq/128, 4),256,3*STAGEB>>>(0,out);

  // decay/exp tables (needed from wkv_contrib onward)
  build_tables<<<Hq,256>>>(log_decay,u);

  // WKV
  wkv_contrib<<<dim3(NCq,BHq),256>>>();
  wkv_scan   <<<BHq,256>>>();
  wkv_main   <<<dim3(NCq,BHq),256,98304>>>();

  // GroupNorm + gate + final LN/quant
  gate_prep<<<NTq,256>>>(gn_g,gn_b,ln_g,ln_b);

  // output projection GEMM -> d_out
  gemm_hmma<<<dim3(Dq/128, NTq/128, 1),256,3*STAGEB>>>(4,out);
}

// round 13
// speedup vs baseline: 1.0691x; 1.0687x over previous
#include <cuda_runtime.h>
#include <cuda_bf16.h>
#include <stdint.h>

#define Bq 4
#define Tq 2048
#define Dq 1024
#define Hq 16
#define Sq 64
#define Cq 64
#define NTq (Bq*Tq)      // 8192 rows
#define NCq (Tq/Cq)      // 32 chunks
#define BHq (Bq*Hq)      // 64 (b,h) pairs

// ---------------- scratch (static __device__, allocation-free) ----------------
__device__ __nv_bfloat16 g_Wb[5][Dq*Dq];   // ternary weights as bf16 (-1,0,1)
__device__ float  g_wpart[5][64];
__device__ float  g_wscale[5];
__device__ __nv_bfloat16 g_Xb[5][NTq*Dq];  // quantized activations as bf16 ints
__device__ float  g_xscale[5][NTq];
__device__ float  g_Y[4][NTq*Dq];          // r,k,v,g projection outputs (fp32)
__device__ float  g_states[BHq*NCq*Sq*Sq]; // per-chunk contributions -> states
__device__ float  g_ywkv[NTq*Dq];          // wkv output in (B,T,D)
// decay tables: [h][t][s], bit-exact replicas of the per-block exp computations
__device__ float  g_ein[Hq*Cq*Sq];         // exp(-t*lw)
__device__ float  g_ekt[Hq*Cq*Sq];         // exp(t*lw)
__device__ float  g_ek1[Hq*Cq*Sq];         // exp((t+1)*lw)
__device__ float  g_ekc[Hq*Cq*Sq];         // exp((C-1-t)*lw)
__device__ float  g_uex[Hq*Sq];            // exp(u)
__device__ float  g_wCt[Hq*Sq];            // exp(C*lw)

// ---------------- compensated-sum helpers ----------------
__device__ __forceinline__ float2 df_comb(float2 a, float2 b){
  float s  = a.x + b.x;
  float bp = s - a.x;
  float er = (a.x - (s - bp)) + (b.x - bp);
  return make_float2(s, a.y + b.y + er);
}
__device__ __forceinline__ void df_acc(float2& s, float v){
  float t=s.x+v; float bp=t-s.x; float er=(s.x-(t-bp))+(v-bp);
  s.x=t; s.y+=er;
}
__device__ __forceinline__ float2 shfl2(float2 v, int o){
  return make_float2(__shfl_xor_sync(0xffffffffu,v.x,o),
                     __shfl_xor_sync(0xffffffffu,v.y,o));
}
// 3-sync block reductions over 256 threads (8 warps)
__device__ __forceinline__ void block_sum2(float2& a, float2& b, float2* r1, float2* r2, int tid){
  #pragma unroll
  for(int o=16;o;o>>=1){ a=df_comb(a,shfl2(a,o)); b=df_comb(b,shfl2(b,o)); }
  __syncthreads();
  if((tid&31)==0){ r1[tid>>5]=a; r2[tid>>5]=b; }
  __syncthreads();
  if(tid<32){
    float2 aa=(tid<8)?r1[tid]:make_float2(0.f,0.f);
    float2 bb=(tid<8)?r2[tid]:make_float2(0.f,0.f);
    #pragma unroll
    for(int o=4;o;o>>=1){ aa=df_comb(aa,shfl2(aa,o)); bb=df_comb(bb,shfl2(bb,o)); }
    if(tid==0){ r1[0]=aa; r2[0]=bb; }
  }
  __syncthreads();
  a=r1[0]; b=r2[0];
}
__device__ __forceinline__ void block_sum1(float2& a, float2* r1, int tid){
  #pragma unroll
  for(int o=16;o;o>>=1) a=df_comb(a,shfl2(a,o));
  __syncthreads();
  if((tid&31)==0) r1[tid>>5]=a;
  __syncthreads();
  if(tid<32){
    float2 aa=(tid<8)?r1[tid]:make_float2(0.f,0.f);
    #pragma unroll
    for(int o=4;o;o>>=1) aa=df_comb(aa,shfl2(aa,o));
    if(tid==0) r1[0]=aa;
  }
  __syncthreads();
  a=r1[0];
}

// exp(n * lw) with exact hi/lo argument split: expf(hi)*(1+lo)
__device__ __forceinline__ float exp_nlw(float n, float lw){
  float hi = __fmul_rn(n, lw);
  float lo = __fmaf_rn(n, lw, -hi);
  return __fmul_rn(expf(hi), __fadd_rn(1.f, lo));
}

__device__ __forceinline__ uint32_t smem_u32(const void* p){
  return (uint32_t)__cvta_generic_to_shared(p);
}

// ---------------- decay table builder (once; bit-exact vs in-kernel formulas) ----
__global__ void build_tables(const float* __restrict__ ld_in, const float* __restrict__ u_in){
  int h = blockIdx.x, tid = threadIdx.x;
  __shared__ float lws[Sq];
  if(tid<Sq){
    float w = expf(-expf(ld_in[h*Sq+tid]));
    float lw = logf(fmaxf(w,1e-38f));
    lws[tid]=lw;
    g_uex[h*Sq+tid]=expf(u_in[h*Sq+tid]);
    g_wCt[h*Sq+tid]=expf(__fmul_rn((float)Cq,lw));
  }
  __syncthreads();
  for(int idx=tid; idx<Cq*Sq; idx+=256){
    int t=idx>>6, s=idx&63;
    float lw=lws[s];
    g_ein[h*Cq*Sq+idx]=exp_nlw(-(float)t, lw);
    g_ekt[h*Cq*Sq+idx]=exp_nlw((float)t, lw);
    g_ek1[h*Cq*Sq+idx]=exp_nlw((float)(t+1), lw);
    g_ekc[h*Cq*Sq+idx]=exp_nlw((float)(Cq-1-t), lw);
  }
}

// ---------------- LN + abs-mean + bf16-int quantize (4 elems/thread) ----------------
__device__ __forceinline__ void ln_quant4(float4 v4, const float* gp, const float* bp,
                                          int j, int bt, float2* r1, float2* r2, int tid){
  float ps = ((v4.x+v4.y)+(v4.z+v4.w));
  float pq = ((__fmul_rn(v4.x,v4.x)+__fmul_rn(v4.y,v4.y))
             +(__fmul_rn(v4.z,v4.z)+__fmul_rn(v4.w,v4.w)));
  float2 s1=make_float2(ps,0.f), s2=make_float2(pq,0.f);
  block_sum2(s1,s2,r1,r2,tid);
  if(tid==0){
    float m0 = __fmul_rn(__fadd_rn(s1.x,s1.y), 1.f/Dq);
    double S1=(double)s1.x+(double)s1.y, S2=(double)s2.x+(double)s2.y;
    double var = S2*(1.0/Dq) - (double)m0*(2.0*S1*(1.0/Dq) - (double)m0);
    float inv0 = (float)(1.0/sqrt(var + 1e-5));
    r2[1]=make_float2(m0,inv0);
  }
  __syncthreads();
  float m=r2[1].x, inv=r2[1].y;
  int d0=tid<<2;
  float4 g4=*(const float4*)&gp[d0];
  float4 b4=*(const float4*)&bp[d0];
  float n0=__fadd_rn(__fmul_rn(__fmul_rn(__fsub_rn(v4.x,m),inv),g4.x),b4.x);
  float n1=__fadd_rn(__fmul_rn(__fmul_rn(__fsub_rn(v4.y,m),inv),g4.y),b4.y);
  float n2=__fadd_rn(__fmul_rn(__fmul_rn(__fsub_rn(v4.z,m),inv),g4.z),b4.z);
  float n3=__fadd_rn(__fmul_rn(__fmul_rn(__fsub_rn(v4.w,m),inv),g4.w),b4.w);
  float2 sa=make_float2(((fabsf(n0)+fabsf(n1))+(fabsf(n2)+fabsf(n3))),0.f);
  block_sum1(sa,r1,tid);
  float am = __fmul_rn(__fadd_rn(sa.x,sa.y), 1.f/Dq);
  float scale = __fdiv_rn(__fmul_rn(fmaxf(am,1e-8f),2.5f), 127.f);
  float q0=rintf(fminf(fmaxf(__fdiv_rn(n0,scale),-127.f),127.f));
  float q1=rintf(fminf(fmaxf(__fdiv_rn(n1,scale),-127.f),127.f));
  float q2=rintf(fminf(fmaxf(__fdiv_rn(n2,scale),-127.f),127.f));
  float q3=rintf(fminf(fmaxf(__fdiv_rn(n3,scale),-127.f),127.f));
  union { __nv_bfloat16 h[4]; uint2 u; } o;
  o.h[0]=__float2bfloat16_rn(q0); o.h[1]=__float2bfloat16_rn(q1);
  o.h[2]=__float2bfloat16_rn(q2); o.h[3]=__float2bfloat16_rn(q3);
  *(uint2*)&g_Xb[j][(size_t)bt*Dq + d0] = o.u;
  if(tid==0) g_xscale[j][bt]=scale;
}

// ---------------- weight quantization ----------------
__global__ void wq_part(const float* __restrict__ pw){
  int j=blockIdx.y, sl=blockIdx.x, tid=threadIdx.x;
  __shared__ float2 r1[8];
  const float* w = pw + j*(Dq*Dq) + sl*16384;
  float2 s=make_float2(0.f,0.f);
  for(int i=tid;i<16384;i+=256) df_acc(s,fabsf(w[i]));
  block_sum1(s,r1,tid);
  if(tid==0) g_wpart[j][sl]=__fadd_rn(s.x,s.y);
}
// fused: computes the global scale (identical fp64 reduction) in thread 0, broadcast.
__global__ void wq_quant(const float* __restrict__ pw){
  __shared__ float sc_sh;
  int gi = blockIdx.x*1024 + threadIdx.x*4;
  int j  = gi >> 20;
  if(threadIdx.x==0){
    double s=0.0;
    for(int i=0;i<64;i++) s+=(double)g_wpart[j][i];
    float sc=fmaxf((float)(s*(1.0/(double)(Dq*Dq))),1e-8f);
    sc_sh=sc;
    g_wscale[j]=sc;
  }
  __syncthreads();
  float sc = sc_sh;
  float4 wv = *(const float4*)&pw[gi];
  union { __nv_bfloat16 h[4]; uint2 u; } o;
  o.h[0]=__float2bfloat16_rn(rintf(fminf(fmaxf(__fdiv_rn(wv.x,sc),-1.f),1.f)));
  o.h[1]=__float2bfloat16_rn(rintf(fminf(fmaxf(__fdiv_rn(wv.y,sc),-1.f),1.f)));
  o.h[2]=__float2bfloat16_rn(rintf(fminf(fmaxf(__fdiv_rn(wv.z,sc),-1.f),1.f)));
  o.h[3]=__float2bfloat16_rn(rintf(fminf(fmaxf(__fdiv_rn(wv.w,sc),-1.f),1.f)));
  *(uint2*)&(((__nv_bfloat16*)g_Wb)[gi]) = o.u;
}

// ---------------- token shift + LN + act quant (one block per (row, proj)) ----------------
__global__ void __launch_bounds__(256) prep_rkvg(
    const float* __restrict__ x,
    const float* __restrict__ mu_r, const float* __restrict__ mu_k,
    const float* __restrict__ mu_v, const float* __restrict__ mu_g,
    const float* __restrict__ ln_g, const float* __restrict__ ln_b){
  int bt=blockIdx.x, j=blockIdx.y;
  int t = bt & (Tq-1);
  int tid=threadIdx.x, d0=tid<<2;
  __shared__ float2 r1[8], r2[8];
  const float* mu = (j==0)?mu_r:(j==1)?mu_k:(j==2)?mu_v:mu_g;
  float4 xv = *(const float4*)&x[(size_t)bt*Dq + d0];
  float4 xp = (t==0)? make_float4(0.f,0.f,0.f,0.f)
                    : *(const float4*)&x[(size_t)(bt-1)*Dq + d0];
  float4 m4 = *(const float4*)&mu[d0];
  float4 v4;
  v4.x=__fadd_rn(xv.x,__fmul_rn(__fsub_rn(xp.x,xv.x),m4.x));
  v4.y=__fadd_rn(xv.y,__fmul_rn(__fsub_rn(xp.y,xv.y),m4.y));
  v4.z=__fadd_rn(xv.z,__fmul_rn(__fsub_rn(xp.z,xv.z),m4.z));
  v4.w=__fadd_rn(xv.w,__fmul_rn(__fsub_rn(xp.w,xv.w),m4.w));
  ln_quant4(v4, ln_g+j*Dq, ln_b+j*Dq, j, bt, r1, r2, tid);
}

// ---------------- HMMA bf16 GEMM: C[8192,1024] = Xb . Wb^T (exact int-in-bf16) ----------------
// CTA 64(M)x128(N), 8 warps as 2(M)x4(N), warp tile 32x32 (acc=32 regs),
// __launch_bounds__(256,3) -> 3 CTAs/SM = 24 warps (vs 16): hide fallback-HMMA latency.
#define RSTRIDE 144            // 128B row + 16B pad: LDSM phases conflict-free
#define AROWS 64
#define BROWS 128
#define NRWS (AROWS+BROWS)     // 192 rows per stage
#define STG (NRWS*RSTRIDE)     // 27648 B per stage; 2 stages = 55296
__device__ __forceinline__ void mma_bf16(float* d, uint32_t a0,uint32_t a1,uint32_t a2,uint32_t a3,
                                         uint32_t b0,uint32_t b1){
  asm volatile("mma.sync.aligned.m16n8k16.row.col.f32.bf16.bf16.f32 "
    "{%0,%1,%2,%3}, {%4,%5,%6,%7}, {%8,%9}, {%0,%1,%2,%3};"
    : "+f"(d[0]),"+f"(d[1]),"+f"(d[2]),"+f"(d[3])
    : "r"(a0),"r"(a1),"r"(a2),"r"(a3),"r"(b0),"r"(b1));
}
__device__ __forceinline__ void ldsm4(uint32_t& r0,uint32_t& r1,uint32_t& r2,uint32_t& r3,
                                      uint32_t addr){
  asm volatile("ldmatrix.sync.aligned.m8n8.x4.shared.b16 {%0,%1,%2,%3}, [%4];"
    : "=r"(r0),"=r"(r1),"=r"(r2),"=r"(r3) : "r"(addr));
}
__device__ __forceinline__ void cp16(uint32_t daddr, const void* gptr){
  asm volatile("cp.async.cg.shared.global [%0], [%1], 16;" :: "r"(daddr), "l"(gptr));
}
__global__ void __launch_bounds__(256,3) gemm_hmma(int jbase, float* __restrict__ dout){
  extern __shared__ char sm8[];
  int j = jbase + blockIdx.z;
  const __nv_bfloat16* Ag = g_Xb[j];
  const __nv_bfloat16* Bg = g_Wb[j];
  float* C = (j==4)? dout : g_Y[j];
  int tid=threadIdx.x;
  int wid=tid>>5, lane=tid&31;
  int g=lane>>2, tig=lane&3;
  int wm=wid>>2, wn=wid&3;                 // 2(M) x 4(N)
  int m0=blockIdx.y*AROWS, n0=blockIdx.x*BROWS;
  int lrow=lane&15, lhi=(lane>>4)*16;

  float acc[2][4][4];
  #pragma unroll
  for(int mi=0;mi<2;mi++)
    #pragma unroll
    for(int ni=0;ni<4;ni++)
      #pragma unroll
      for(int q=0;q<4;q++) acc[mi][ni][q]=0.f;

  // copy slots: 192 rows x 8 chunks(16B) = 1536 chunks; 6 per thread
  const char* gsrc[6]; uint32_t sdst[6];
  #pragma unroll
  for(int i=0;i<6;i++){
    int cidx = tid + i*256;
    int r = cidx>>3, q = cidx&7;
    const char* gb = (r<AROWS)
        ? (const char*)(Ag + (size_t)(m0+r)*Dq)
        : (const char*)(Bg + (size_t)(n0+(r-AROWS))*Dq);
    gsrc[i] = gb + q*16;
    sdst[i] = smem_u32(sm8 + r*RSTRIDE + q*16);
  }

  // prologue: stage 0
  #pragma unroll
  for(int i=0;i<6;i++) cp16(sdst[i], gsrc[i]);
  asm volatile("cp.async.commit_group;");

  for(int kt=0;kt<16;kt++){
    asm volatile("cp.async.wait_group 0;");
    __syncthreads();                 // all warps done with buf^1 compute
    if(kt+1<16){
      uint32_t so = (uint32_t)(((kt+1)&1))*STG;
      int go = (kt+1)*128;
      #pragma unroll
      for(int i=0;i<6;i++) cp16(sdst[i]+so, gsrc[i]+go);
      asm volatile("cp.async.commit_group;");
    }
    const char* Ab = sm8 + (kt&1)*STG;
    const char* Bb = Ab + AROWS*RSTRIDE;
    #pragma unroll
    for(int s=0;s<4;s++){
      uint32_t af[2][4];
      #pragma unroll
      for(int mi=0;mi<2;mi++){
        uint32_t ad = smem_u32(Ab + (wm*32+mi*16+lrow)*RSTRIDE + s*32 + lhi);
        ldsm4(af[mi][0],af[mi][1],af[mi][2],af[mi][3], ad);
      }
      uint32_t b0a[4], b1a[4];
      #pragma unroll
      for(int nb2=0;nb2<2;nb2++){
        uint32_t bd = smem_u32(Bb + (wn*32+nb2*16+lrow)*RSTRIDE + s*32 + lhi);
        uint32_t r0,r1,r2,r3;
        ldsm4(r0,r1,r2,r3, bd);
        b0a[2*nb2]=r0; b0a[2*nb2+1]=r1; b1a[2*nb2]=r2; b1a[2*nb2+1]=r3;
      }
      #pragma unroll
      for(int mi=0;mi<2;mi++)
        #pragma unroll
        for(int ni=0;ni<4;ni++)
          mma_bf16(acc[mi][ni], af[mi][0],af[mi][1],af[mi][2],af[mi][3],
                   b0a[ni], b1a[ni]);
    }
  }

  float ws=g_wscale[j];
  #pragma unroll
  for(int mi=0;mi<2;mi++){
    int r0 = m0 + wm*32 + mi*16 + g;
    float sc0=__fmul_rn(g_xscale[j][r0  ],ws);
    float sc1=__fmul_rn(g_xscale[j][r0+8],ws);
    #pragma unroll
    for(int ni=0;ni<4;ni++){
      int col = n0 + wn*32 + ni*8 + tig*2;
      float2 o0, o1;
      o0.x=__fmul_rn(acc[mi][ni][0],sc0);
      o0.y=__fmul_rn(acc[mi][ni][1],sc0);
      o1.x=__fmul_rn(acc[mi][ni][2],sc1);
      o1.y=__fmul_rn(acc[mi][ni][3],sc1);
      *(float2*)&C[(size_t)r0*Dq + col]     = o0;
      *(float2*)&C[(size_t)(r0+8)*Dq + col] = o1;
    }
  }
}

// ---------------- WKV phase A: per-chunk contribution G_c = (K .* w^{C-1-t})^T @ V ----------------
__global__ void wkv_contrib(){
  int c = blockIdx.x, bh = blockIdx.y;
  int b = bh>>4, h = bh&15;
  int tid = threadIdx.x;
  __shared__ float kw[Cq*Sq], vs[Cq*Sq];
  const float* Yk = g_Y[1];
  const float* Yv = g_Y[2];
  const float* ekc = g_ekc + h*Cq*Sq;
  int base = (b*Tq + c*Cq)*Dq + h*Sq;
  for(int idx=tid; idx<Cq*Sq; idx+=256){
    int t=idx>>6, s=idx&63;
    kw[idx] = __fmul_rn(Yk[base + t*Dq + s], ekc[idx]);
    vs[idx] = Yv[base + t*Dq + s];
  }
  __syncthreads();
  int ts=(tid>>4)*4, to=(tid&15)*4;
  float acc[4][4]={};
  for(int t=0;t<Cq;t++){
    float4 a=*(const float4*)&kw[t*Sq+ts];
    float4 v=*(const float4*)&vs[t*Sq+to];
    acc[0][0]+=a.x*v.x; acc[0][1]+=a.x*v.y; acc[0][2]+=a.x*v.z; acc[0][3]+=a.x*v.w;
    acc[1][0]+=a.y*v.x; acc[1][1]+=a.y*v.y; acc[1][2]+=a.y*v.z; acc[1][3]+=a.y*v.w;
    acc[2][0]+=a.z*v.x; acc[2][1]+=a.z*v.y; acc[2][2]+=a.z*v.z; acc[2][3]+=a.z*v.w;
    acc[3][0]+=a.w*v.x; acc[3][1]+=a.w*v.y; acc[3][2]+=a.w*v.z; acc[3][3]+=a.w*v.w;
  }
  float* G = &g_states[(bh*NCq + c)*Sq*Sq];
  #pragma unroll
  for(int i=0;i<4;i++)
    #pragma unroll
    for(int jj=0;jj<4;jj++)
      G[(ts+i)*Sq + to+jj]=acc[i][jj];
}

// ---------------- WKV phase B: scan ----------------
__global__ void wkv_scan(){
  int bh = blockIdx.x, h = bh&15;
  int tid = threadIdx.x;
  __shared__ float wC[Sq];
  if(tid<Sq) wC[tid]=g_wCt[h*Sq+tid];
  __syncthreads();
  for(int e=tid; e<Sq*Sq; e+=256){
    float wc = wC[e>>6];
    float cur = 0.f;
    float* Gp = &g_states[bh*NCq*Sq*Sq + e];
    for(int c=0;c<NCq;c++){
      float gv = Gp[c*Sq*Sq];
      Gp[c*Sq*Sq]=cur;
      cur = __fadd_rn(__fmul_rn(wc,cur), gv);
    }
  }
}

// ---------------- WKV phase C: per-chunk output ----------------
__global__ void __launch_bounds__(256) wkv_main(){
  extern __shared__ float sm[];
  float* rpT = sm;               // [S][C] : r * w^{-t}
  float* rwT = sm + 4096;        // [S][C] : r * w^{t+1}
  float* kpT = sm + 8192;        // [S][C] : k * w^{t}
  float* vs  = sm + 12288;       // [C][S]
  float* st  = sm + 16384;       // [S][S] state before chunk
  float* PT  = sm + 20480;       // [C(i)][C(t)] masked
  __shared__ float uex[Sq], dv[Cq];

  int c = blockIdx.x, bh = blockIdx.y;
  int b = bh>>4, h = bh&15;
  int tid = threadIdx.x;
  if(tid<Sq) uex[tid]=g_uex[h*Sq+tid];
  const float* Yr=g_Y[0]; const float* Yk=g_Y[1]; const float* Yv=g_Y[2];
  const float* ein = g_ein + h*Cq*Sq;
  const float* ekt = g_ekt + h*Cq*Sq;
  const float* ek1 = g_ek1 + h*Cq*Sq;
  int base = (b*Tq + c*Cq)*Dq + h*Sq;
  const float* Gst = &g_states[(bh*NCq + c)*Sq*Sq];
  for(int idx=tid; idx<Cq*Sq; idx+=256){
    int t=idx>>6, s=idx&63;
    float rv=Yr[base + t*Dq + s];
    float kv=Yk[base + t*Dq + s];
    float vv=Yv[base + t*Dq + s];
    rpT[s*Cq+t]=__fmul_rn(rv,ein[idx]);
    rwT[s*Cq+t]=__fmul_rn(rv,ek1[idx]);
    kpT[s*Cq+t]=__fmul_rn(kv,ekt[idx]);
    vs[t*Sq+s]=vv;
    st[idx]=Gst[idx];
  }
  __syncthreads();
  if(tid<Cq){
    float a=0.f;
    for(int s=0;s<Sq;s++) a += rpT[s*Cq+tid]*kpT[s*Cq+tid]*uex[s];
    dv[tid]=a;
  }
  __syncthreads();
  int tt=(tid>>4)*4, ti=(tid&15)*4;
  {
    float acc[4][4]={};
    for(int s=0;s<Sq;s++){
      float4 a=*(const float4*)&rpT[s*Cq+tt];
      float4 k4=*(const float4*)&kpT[s*Cq+ti];
      acc[0][0]+=a.x*k4.x; acc[0][1]+=a.x*k4.y; acc[0][2]+=a.x*k4.z; acc[0][3]+=a.x*k4.w;
      acc[1][0]+=a.y*k4.x; acc[1][1]+=a.y*k4.y; acc[1][2]+=a.y*k4.z; acc[1][3]+=a.y*k4.w;
      acc[2][0]+=a.z*k4.x; acc[2][1]+=a.z*k4.y; acc[2][2]+=a.z*k4.z; acc[2][3]+=a.z*k4.w;
      acc[3][0]+=a.w*k4.x; acc[3][1]+=a.w*k4.y; acc[3][2]+=a.w*k4.z; acc[3][3]+=a.w*k4.w;
    }
    #pragma unroll
    for(int i=0;i<4;i++)
      #pragma unroll
      for(int jj=0;jj<4;jj++)
        PT[(ti+jj)*Cq + (tt+i)] = (ti+jj >= tt+i) ? acc[i][jj] : 0.f;
  }
  __syncthreads();
  int to = ti;
  {
    float acc[4][4]={};
    for(int l=0;l<Sq;l++){
      float4 a =*(const float4*)&PT[l*Cq+tt];
      float4 v4=*(const float4*)&vs[l*Sq+to];
      float4 r4=*(const float4*)&rwT[l*Cq+tt];
      float4 s4=*(const float4*)&st[l*Sq+to];
      acc[0][0]+=a.x*v4.x+r4.x*s4.x; acc[0][1]+=a.x*v4.y+r4.x*s4.y;
      acc[0][2]+=a.x*v4.z+r4.x*s4.z; acc[0][3]+=a.x*v4.w+r4.x*s4.w;
      acc[1][0]+=a.y*v4.x+r4.y*s4.x; acc[1][1]+=a.y*v4.y+r4.y*s4.y;
      acc[1][2]+=a.y*v4.z+r4.y*s4.z; acc[1][3]+=a.y*v4.w+r4.y*s4.w;
      acc[2][0]+=a.z*v4.x+r4.z*s4.x; acc[2][1]+=a.z*v4.y+r4.z*s4.y;
      acc[2][2]+=a.z*v4.z+r4.z*s4.z; acc[2][3]+=a.z*v4.w+r4.z*s4.w;
      acc[3][0]+=a.w*v4.x+r4.w*s4.x; acc[3][1]+=a.w*v4.y+r4.w*s4.y;
      acc[3][2]+=a.w*v4.z+r4.w*s4.z; acc[3][3]+=a.w*v4.w+r4.w*s4.w;
    }
    #pragma unroll
    for(int i=0;i<4;i++){
      float dd = dv[tt+i];
      #pragma unroll
      for(int jj=0;jj<4;jj++){
        float y = __fadd_rn(acc[i][jj], __fmul_rn(dd,vs[(tt+i)*Sq + to+jj]));
        g_ywkv[(b*Tq + c*Cq + tt+i)*Dq + h*Sq + to+jj] = y;
      }
    }
  }
}

// ---------------- GroupNorm + SiLU gate + LN + quant ----------------
__global__ void __launch_bounds__(256) gate_prep(
    const float* __restrict__ gn_g, const float* __restrict__ gn_b,
    const float* __restrict__ ln_g, const float* __restrict__ ln_b){
  int bt=blockIdx.x, tid=threadIdx.x, d0=tid<<2;
  __shared__ float yr[Dq], gm[Hq], gi[Hq];
  __shared__ float2 r1[8], r2[8];
  float4 y4 = *(const float4*)&g_ywkv[(size_t)bt*Dq + d0];
  *(float4*)&yr[d0] = y4;
  __syncthreads();
  int w=tid>>5, lane=tid&31;
  for(int gg=2*w; gg<2*w+2; gg++){
    float e1=yr[gg*Sq+lane], e2=yr[gg*Sq+32+lane];
    float2 s = df_comb(make_float2(e1,0.f), make_float2(e2,0.f));
    #pragma unroll
    for(int o=16;o;o>>=1) s = df_comb(s, shfl2(s,o));
    float m=__fmul_rn(s.x+s.y, 1.f/Sq);
    float d1=__fsub_rn(e1,m), d2=__fsub_rn(e2,m);
    float2 s2 = df_comb(make_float2(__fmul_rn(d1,d1),0.f), make_float2(__fmul_rn(d2,d2),0.f));
    #pragma unroll
    for(int o=16;o;o>>=1) s2 = df_comb(s2, shfl2(s2,o));
    if(lane==0){
      gm[gg]=m;
      float ve=__fadd_rn(__fmul_rn(s2.x+s2.y, 1.f/Sq), 1e-5f);
      gi[gg]=(float)(1.0/sqrt((double)ve));
    }
  }
  __syncthreads();
  int gg=d0>>6;
  float4 gg4=*(const float4*)&gn_g[d0];
  float4 gb4=*(const float4*)&gn_b[d0];
  float4 gv4=*(const float4*)&g_Y[3][(size_t)bt*Dq + d0];
  float mm=gm[gg], ii=gi[gg];
  float4 v4;
  {
    float yn=__fadd_rn(__fmul_rn(__fmul_rn(__fsub_rn(y4.x,mm),ii),gg4.x),gb4.x);
    float sg=__fdiv_rn(1.f,__fadd_rn(1.f,expf(-gv4.x)));
    v4.x=__fmul_rn(yn,__fmul_rn(gv4.x,sg));
    yn=__fadd_rn(__fmul_rn(__fmul_rn(__fsub_rn(y4.y,mm),ii),gg4.y),gb4.y);
    sg=__fdiv_rn(1.f,__fadd_rn(1.f,expf(-gv4.y)));
    v4.y=__fmul_rn(yn,__fmul_rn(gv4.y,sg));
    yn=__fadd_rn(__fmul_rn(__fmul_rn(__fsub_rn(y4.z,mm),ii),gg4.z),gb4.z);
    sg=__fdiv_rn(1.f,__fadd_rn(1.f,expf(-gv4.z)));
    v4.z=__fmul_rn(yn,__fmul_rn(gv4.z,sg));
    yn=__fadd_rn(__fmul_rn(__fmul_rn(__fsub_rn(y4.w,mm),ii),gg4.w),gb4.w);
    sg=__fdiv_rn(1.f,__fadd_rn(1.f,expf(-gv4.w)));
    v4.w=__fmul_rn(yn,__fmul_rn(gv4.w,sg));
  }
  ln_quant4(v4, ln_g+4*Dq, ln_b+4*Dq, 4, bt, r1, r2, tid);
}

// ---------------- launch ----------------
extern "C" void kernel_launch(void* const* d_in, const int* in_sizes, int n_in,
                              void* d_out, int out_size){
  const float* x        =(const float*)d_in[0];
  const float* mu_r     =(const float*)d_in[1];
  const float* mu_k     =(const float*)d_in[2];
  const float* mu_v     =(const float*)d_in[3];
  const float* mu_g     =(const float*)d_in[4];
  const float* log_decay=(const float*)d_in[5];
  const float* u        =(const float*)d_in[6];
  const float* proj_w   =(const float*)d_in[7];
  const float* ln_g     =(const float*)d_in[8];
  const float* ln_b     =(const float*)d_in[9];
  const float* gn_g     =(const float*)d_in[10];
  const float* gn_b     =(const float*)d_in[11];
  float* out=(float*)d_out;

  cudaFuncSetAttribute(wkv_main,  cudaFuncAttributeMaxDynamicSharedMemorySize, 98304);
  cudaFuncSetAttribute(gemm_hmma, cudaFuncAttributeMaxDynamicSharedMemorySize, 2*STG);

  // (0) weight abs-sum partials
  wq_part <<<dim3(64,5),256>>>(proj_w);
  // (1) token shift + LN + act quant for r,k,v,g
  prep_rkvg<<<dim3(NTq,4),256>>>(x,mu_r,mu_k,mu_v,mu_g,ln_g,ln_b);
  // (2) weight scale + quantize (fused)
  wq_quant<<<5120,256>>>(proj_w);
  // (3) 4 projection GEMMs, batched  <-- profiled launch index
  gemm_hmma<<<dim3(Dq/BROWS, NTq/AROWS, 4),256,2*STG>>>(0,out);

  // decay/exp tables (needed from wkv_contrib onward)
  build_tables<<<Hq,256>>>(log_decay,u);

  // WKV
  wkv_contrib<<<dim3(NCq,BHq),256>>>();
  wkv_scan   <<<BHq,256>>>();
  wkv_main   <<<dim3(NCq,BHq),256,98304>>>();

  // GroupNorm + gate + final LN/quant
  gate_prep<<<NTq,256>>>(gn_g,gn_b,ln_g,ln_b);

  // output projection GEMM -> d_out
  gemm_hmma<<<dim3(Dq/BROWS, NTq/AROWS, 1),256,2*STG>>>(4,out);
}

// round 14
// speedup vs baseline: 1.1294x; 1.0564x over previous
#include <cuda_runtime.h>
#include <cuda_bf16.h>
#include <stdint.h>

#define Bq 4
#define Tq 2048
#define Dq 1024
#define Hq 16
#define Sq 64
#define Cq 64
#define NTq (Bq*Tq)      // 8192 rows
#define NCq (Tq/Cq)      // 32 chunks
#define BHq (Bq*Hq)      // 64 (b,h) pairs

// ---------------- scratch (static __device__, allocation-free) ----------------
__device__ __nv_bfloat16 g_Wb[5][Dq*Dq];   // ternary weights as bf16 (-1,0,1)
__device__ float  g_wpart[5][64];
__device__ float  g_wscale[5];
__device__ __nv_bfloat16 g_Xb[5][NTq*Dq];  // quantized activations as bf16 ints
__device__ float  g_xscale[5][NTq];
__device__ float  g_Y[4][NTq*Dq];          // r,k,v,g projection outputs (fp32)
__device__ float  g_states[BHq*NCq*Sq*Sq]; // per-chunk contributions -> states
__device__ float  g_ywkv[NTq*Dq];          // wkv output in (B,T,D)
// decay tables: [h][t][s], bit-exact replicas of the per-block exp computations
__device__ float  g_ein[Hq*Cq*Sq];         // exp(-t*lw)
__device__ float  g_ekt[Hq*Cq*Sq];         // exp(t*lw)
__device__ float  g_ek1[Hq*Cq*Sq];         // exp((t+1)*lw)
__device__ float  g_ekc[Hq*Cq*Sq];         // exp((C-1-t)*lw)
__device__ float  g_uex[Hq*Sq];            // exp(u)
__device__ float  g_wCt[Hq*Sq];            // exp(C*lw)

// ---------------- compensated-sum helpers ----------------
__device__ __forceinline__ float2 df_comb(float2 a, float2 b){
  float s  = a.x + b.x;
  float bp = s - a.x;
  float er = (a.x - (s - bp)) + (b.x - bp);
  return make_float2(s, a.y + b.y + er);
}
__device__ __forceinline__ void df_acc(float2& s, float v){
  float t=s.x+v; float bp=t-s.x; float er=(s.x-(t-bp))+(v-bp);
  s.x=t; s.y+=er;
}
__device__ __forceinline__ float2 shfl2(float2 v, int o){
  return make_float2(__shfl_xor_sync(0xffffffffu,v.x,o),
                     __shfl_xor_sync(0xffffffffu,v.y,o));
}
// 3-sync block reductions over 256 threads (8 warps)
__device__ __forceinline__ void block_sum2(float2& a, float2& b, float2* r1, float2* r2, int tid){
  #pragma unroll
  for(int o=16;o;o>>=1){ a=df_comb(a,shfl2(a,o)); b=df_comb(b,shfl2(b,o)); }
  __syncthreads();
  if((tid&31)==0){ r1[tid>>5]=a; r2[tid>>5]=b; }
  __syncthreads();
  if(tid<32){
    float2 aa=(tid<8)?r1[tid]:make_float2(0.f,0.f);
    float2 bb=(tid<8)?r2[tid]:make_float2(0.f,0.f);
    #pragma unroll
    for(int o=4;o;o>>=1){ aa=df_comb(aa,shfl2(aa,o)); bb=df_comb(bb,shfl2(bb,o)); }
    if(tid==0){ r1[0]=aa; r2[0]=bb; }
  }
  __syncthreads();
  a=r1[0]; b=r2[0];
}
__device__ __forceinline__ void block_sum1(float2& a, float2* r1, int tid){
  #pragma unroll
  for(int o=16;o;o>>=1) a=df_comb(a,shfl2(a,o));
  __syncthreads();
  if((tid&31)==0) r1[tid>>5]=a;
  __syncthreads();
  if(tid<32){
    float2 aa=(tid<8)?r1[tid]:make_float2(0.f,0.f);
    #pragma unroll
    for(int o=4;o;o>>=1) aa=df_comb(aa,shfl2(aa,o));
    if(tid==0) r1[0]=aa;
  }
  __syncthreads();
  a=r1[0];
}

// exp(n * lw) with exact hi/lo argument split: expf(hi)*(1+lo)
__device__ __forceinline__ float exp_nlw(float n, float lw){
  float hi = __fmul_rn(n, lw);
  float lo = __fmaf_rn(n, lw, -hi);
  return __fmul_rn(expf(hi), __fadd_rn(1.f, lo));
}

__device__ __forceinline__ uint32_t smem_u32(const void* p){
  return (uint32_t)__cvta_generic_to_shared(p);
}

// ---------------- decay table builder (once; bit-exact vs in-kernel formulas) ----
__global__ void build_tables(const float* __restrict__ ld_in, const float* __restrict__ u_in){
  int h = blockIdx.x, tid = threadIdx.x;
  __shared__ float lws[Sq];
  if(tid<Sq){
    float w = expf(-expf(ld_in[h*Sq+tid]));
    float lw = logf(fmaxf(w,1e-38f));
    lws[tid]=lw;
    g_uex[h*Sq+tid]=expf(u_in[h*Sq+tid]);
    g_wCt[h*Sq+tid]=expf(__fmul_rn((float)Cq,lw));
  }
  __syncthreads();
  for(int idx=tid; idx<Cq*Sq; idx+=256){
    int t=idx>>6, s=idx&63;
    float lw=lws[s];
    g_ein[h*Cq*Sq+idx]=exp_nlw(-(float)t, lw);
    g_ekt[h*Cq*Sq+idx]=exp_nlw((float)t, lw);
    g_ek1[h*Cq*Sq+idx]=exp_nlw((float)(t+1), lw);
    g_ekc[h*Cq*Sq+idx]=exp_nlw((float)(Cq-1-t), lw);
  }
}

// ---------------- LN + abs-mean + bf16-int quantize (4 elems/thread) ----------------
__device__ __forceinline__ void ln_quant4(float4 v4, const float* gp, const float* bp,
                                          int j, int bt, float2* r1, float2* r2, int tid){
  float ps = ((v4.x+v4.y)+(v4.z+v4.w));
  float pq = ((__fmul_rn(v4.x,v4.x)+__fmul_rn(v4.y,v4.y))
             +(__fmul_rn(v4.z,v4.z)+__fmul_rn(v4.w,v4.w)));
  float2 s1=make_float2(ps,0.f), s2=make_float2(pq,0.f);
  block_sum2(s1,s2,r1,r2,tid);
  if(tid==0){
    float m0 = __fmul_rn(__fadd_rn(s1.x,s1.y), 1.f/Dq);
    double S1=(double)s1.x+(double)s1.y, S2=(double)s2.x+(double)s2.y;
    double var = S2*(1.0/Dq) - (double)m0*(2.0*S1*(1.0/Dq) - (double)m0);
    float inv0 = (float)(1.0/sqrt(var + 1e-5));
    r2[1]=make_float2(m0,inv0);
  }
  __syncthreads();
  float m=r2[1].x, inv=r2[1].y;
  int d0=tid<<2;
  float4 g4=*(const float4*)&gp[d0];
  float4 b4=*(const float4*)&bp[d0];
  float n0=__fadd_rn(__fmul_rn(__fmul_rn(__fsub_rn(v4.x,m),inv),g4.x),b4.x);
  float n1=__fadd_rn(__fmul_rn(__fmul_rn(__fsub_rn(v4.y,m),inv),g4.y),b4.y);
  float n2=__fadd_rn(__fmul_rn(__fmul_rn(__fsub_rn(v4.z,m),inv),g4.z),b4.z);
  float n3=__fadd_rn(__fmul_rn(__fmul_rn(__fsub_rn(v4.w,m),inv),g4.w),b4.w);
  float2 sa=make_float2(((fabsf(n0)+fabsf(n1))+(fabsf(n2)+fabsf(n3))),0.f);
  block_sum1(sa,r1,tid);
  float am = __fmul_rn(__fadd_rn(sa.x,sa.y), 1.f/Dq);
  float scale = __fdiv_rn(__fmul_rn(fmaxf(am,1e-8f),2.5f), 127.f);
  float q0=rintf(fminf(fmaxf(__fdiv_rn(n0,scale),-127.f),127.f));
  float q1=rintf(fminf(fmaxf(__fdiv_rn(n1,scale),-127.f),127.f));
  float q2=rintf(fminf(fmaxf(__fdiv_rn(n2,scale),-127.f),127.f));
  float q3=rintf(fminf(fmaxf(__fdiv_rn(n3,scale),-127.f),127.f));
  union { __nv_bfloat16 h[4]; uint2 u; } o;
  o.h[0]=__float2bfloat16_rn(q0); o.h[1]=__float2bfloat16_rn(q1);
  o.h[2]=__float2bfloat16_rn(q2); o.h[3]=__float2bfloat16_rn(q3);
  *(uint2*)&g_Xb[j][(size_t)bt*Dq + d0] = o.u;
  if(tid==0) g_xscale[j][bt]=scale;
}

// ---------------- weight quantization ----------------
__global__ void wq_part(const float* __restrict__ pw){
  int j=blockIdx.y, sl=blockIdx.x, tid=threadIdx.x;
  __shared__ float2 r1[8];
  const float* w = pw + j*(Dq*Dq) + sl*16384;
  float2 s=make_float2(0.f,0.f);
  for(int i=tid;i<16384;i+=256) df_acc(s,fabsf(w[i]));
  block_sum1(s,r1,tid);
  if(tid==0) g_wpart[j][sl]=__fadd_rn(s.x,s.y);
}
// fused: computes the global scale (identical fp64 reduction) in thread 0, broadcast.
__global__ void wq_quant(const float* __restrict__ pw){
  __shared__ float sc_sh;
  int gi = blockIdx.x*1024 + threadIdx.x*4;
  int j  = gi >> 20;
  if(threadIdx.x==0){
    double s=0.0;
    for(int i=0;i<64;i++) s+=(double)g_wpart[j][i];
    float sc=fmaxf((float)(s*(1.0/(double)(Dq*Dq))),1e-8f);
    sc_sh=sc;
    g_wscale[j]=sc;
  }
  __syncthreads();
  float sc = sc_sh;
  float4 wv = *(const float4*)&pw[gi];
  union { __nv_bfloat16 h[4]; uint2 u; } o;
  o.h[0]=__float2bfloat16_rn(rintf(fminf(fmaxf(__fdiv_rn(wv.x,sc),-1.f),1.f)));
  o.h[1]=__float2bfloat16_rn(rintf(fminf(fmaxf(__fdiv_rn(wv.y,sc),-1.f),1.f)));
  o.h[2]=__float2bfloat16_rn(rintf(fminf(fmaxf(__fdiv_rn(wv.z,sc),-1.f),1.f)));
  o.h[3]=__float2bfloat16_rn(rintf(fminf(fmaxf(__fdiv_rn(wv.w,sc),-1.f),1.f)));
  *(uint2*)&(((__nv_bfloat16*)g_Wb)[gi]) = o.u;
}

// ---------------- token shift + LN + act quant (one block per (row, proj)) ----------------
__global__ void __launch_bounds__(256) prep_rkvg(
    const float* __restrict__ x,
    const float* __restrict__ mu_r, const float* __restrict__ mu_k,
    const float* __restrict__ mu_v, const float* __restrict__ mu_g,
    const float* __restrict__ ln_g, const float* __restrict__ ln_b){
  int bt=blockIdx.x, j=blockIdx.y;
  int t = bt & (Tq-1);
  int tid=threadIdx.x, d0=tid<<2;
  __shared__ float2 r1[8], r2[8];
  const float* mu = (j==0)?mu_r:(j==1)?mu_k:(j==2)?mu_v:mu_g;
  float4 xv = *(const float4*)&x[(size_t)bt*Dq + d0];
  float4 xp = (t==0)? make_float4(0.f,0.f,0.f,0.f)
                    : *(const float4*)&x[(size_t)(bt-1)*Dq + d0];
  float4 m4 = *(const float4*)&mu[d0];
  float4 v4;
  v4.x=__fadd_rn(xv.x,__fmul_rn(__fsub_rn(xp.x,xv.x),m4.x));
  v4.y=__fadd_rn(xv.y,__fmul_rn(__fsub_rn(xp.y,xv.y),m4.y));
  v4.z=__fadd_rn(xv.z,__fmul_rn(__fsub_rn(xp.z,xv.z),m4.z));
  v4.w=__fadd_rn(xv.w,__fmul_rn(__fsub_rn(xp.w,xv.w),m4.w));
  ln_quant4(v4, ln_g+j*Dq, ln_b+j*Dq, j, bt, r1, r2, tid);
}

// ---------------- HMMA bf16 GEMM: C[8192,1024] = Xb . Wb^T (exact int-in-bf16) ----------------
// CTA 64(M)x128(N), 8 warps as 2(M)x4(N), warp tile 32x32 (acc=32 regs),
// __launch_bounds__(256,4) -> target 4 CTAs/SM = 32 warps. Copy addresses
// recomputed per prefetch (no pinned pointer arrays) to cut register pressure.
#define RSTRIDE 144            // 128B row + 16B pad: LDSM phases conflict-free
#define AROWS 64
#define BROWS 128
#define NRWS (AROWS+BROWS)     // 192 rows per stage
#define STG (NRWS*RSTRIDE)     // 27648 B per stage; 2 stages = 55296
__device__ __forceinline__ void mma_bf16(float* d, uint32_t a0,uint32_t a1,uint32_t a2,uint32_t a3,
                                         uint32_t b0,uint32_t b1){
  asm volatile("mma.sync.aligned.m16n8k16.row.col.f32.bf16.bf16.f32 "
    "{%0,%1,%2,%3}, {%4,%5,%6,%7}, {%8,%9}, {%0,%1,%2,%3};"
    : "+f"(d[0]),"+f"(d[1]),"+f"(d[2]),"+f"(d[3])
    : "r"(a0),"r"(a1),"r"(a2),"r"(a3),"r"(b0),"r"(b1));
}
__device__ __forceinline__ void ldsm4(uint32_t& r0,uint32_t& r1,uint32_t& r2,uint32_t& r3,
                                      uint32_t addr){
  asm volatile("ldmatrix.sync.aligned.m8n8.x4.shared.b16 {%0,%1,%2,%3}, [%4];"
    : "=r"(r0),"=r"(r1),"=r"(r2),"=r"(r3) : "r"(addr));
}
__device__ __forceinline__ void cp16(uint32_t daddr, const void* gptr){
  asm volatile("cp.async.cg.shared.global [%0], [%1], 16;" :: "r"(daddr), "l"(gptr));
}
__global__ void __launch_bounds__(256,4) gemm_hmma(int jbase, float* __restrict__ dout){
  extern __shared__ char sm8[];
  int j = jbase + blockIdx.z;
  const __nv_bfloat16* Ag = g_Xb[j];
  const __nv_bfloat16* Bg = g_Wb[j];
  float* C = (j==4)? dout : g_Y[j];
  int tid=threadIdx.x;
  int wid=tid>>5, lane=tid&31;
  int g=lane>>2, tig=lane&3;
  int wm=wid>>2, wn=wid&3;                 // 2(M) x 4(N)
  int m0=blockIdx.y*AROWS, n0=blockIdx.x*BROWS;
  int lrow=lane&15, lhi=(lane>>4)*16;

  float acc[2][4][4];
  #pragma unroll
  for(int mi=0;mi<2;mi++)
    #pragma unroll
    for(int ni=0;ni<4;ni++)
      #pragma unroll
      for(int q=0;q<4;q++) acc[mi][ni][q]=0.f;

  // copy geometry (recomputed each prefetch; keeps only row/q in flight)
  int crow = tid>>3, cq = (tid&7)*16;      // 6 rows/thread stride 32
  // prologue: stage 0
  #pragma unroll
  for(int i=0;i<6;i++){
    int r = crow + i*32;
    const char* gb = (r<AROWS)
        ? (const char*)(Ag + (size_t)(m0+r)*Dq)
        : (const char*)(Bg + (size_t)(n0+(r-AROWS))*Dq);
    cp16(smem_u32(sm8 + r*RSTRIDE + cq), gb + cq);
  }
  asm volatile("cp.async.commit_group;");

  for(int kt=0;kt<16;kt++){
    asm volatile("cp.async.wait_group 0;");
    __syncthreads();                 // all warps done with buf^1 compute
    if(kt+1<16){
      uint32_t so = (uint32_t)(((kt+1)&1))*STG;
      int go = (kt+1)*128;
      #pragma unroll
      for(int i=0;i<6;i++){
        int r = crow + i*32;
        const char* gb = (r<AROWS)
            ? (const char*)(Ag + (size_t)(m0+r)*Dq)
            : (const char*)(Bg + (size_t)(n0+(r-AROWS))*Dq);
        cp16(smem_u32(sm8 + r*RSTRIDE + cq) + so, gb + cq + go);
      }
      asm volatile("cp.async.commit_group;");
    }
    const char* Ab = sm8 + (kt&1)*STG;
    const char* Bb = Ab + AROWS*RSTRIDE;
    #pragma unroll
    for(int s=0;s<4;s++){
      uint32_t af[2][4];
      #pragma unroll
      for(int mi=0;mi<2;mi++){
        uint32_t ad = smem_u32(Ab + (wm*32+mi*16+lrow)*RSTRIDE + s*32 + lhi);
        ldsm4(af[mi][0],af[mi][1],af[mi][2],af[mi][3], ad);
      }
      uint32_t b0a[4], b1a[4];
      #pragma unroll
      for(int nb2=0;nb2<2;nb2++){
        uint32_t bd = smem_u32(Bb + (wn*32+nb2*16+lrow)*RSTRIDE + s*32 + lhi);
        uint32_t r0,r1,r2,r3;
        ldsm4(r0,r1,r2,r3, bd);
        b0a[2*nb2]=r0; b0a[2*nb2+1]=r1; b1a[2*nb2]=r2; b1a[2*nb2+1]=r3;
      }
      #pragma unroll
      for(int mi=0;mi<2;mi++)
        #pragma unroll
        for(int ni=0;ni<4;ni++)
          mma_bf16(acc[mi][ni], af[mi][0],af[mi][1],af[mi][2],af[mi][3],
                   b0a[ni], b1a[ni]);
    }
  }

  float ws=g_wscale[j];
  #pragma unroll
  for(int mi=0;mi<2;mi++){
    int r0 = m0 + wm*32 + mi*16 + g;
    float sc0=__fmul_rn(g_xscale[j][r0  ],ws);
    float sc1=__fmul_rn(g_xscale[j][r0+8],ws);
    #pragma unroll
    for(int ni=0;ni<4;ni++){
      int col = n0 + wn*32 + ni*8 + tig*2;
      float2 o0, o1;
      o0.x=__fmul_rn(acc[mi][ni][0],sc0);
      o0.y=__fmul_rn(acc[mi][ni][1],sc0);
      o1.x=__fmul_rn(acc[mi][ni][2],sc1);
      o1.y=__fmul_rn(acc[mi][ni][3],sc1);
      *(float2*)&C[(size_t)r0*Dq + col]     = o0;
      *(float2*)&C[(size_t)(r0+8)*Dq + col] = o1;
    }
  }
}

// ---------------- WKV phase A: per-chunk contribution G_c = (K .* w^{C-1-t})^T @ V ----------------
__global__ void wkv_contrib(){
  int c = blockIdx.x, bh = blockIdx.y;
  int b = bh>>4, h = bh&15;
  int tid = threadIdx.x;
  __shared__ float kw[Cq*Sq], vs[Cq*Sq];
  const float* Yk = g_Y[1];
  const float* Yv = g_Y[2];
  const float* ekc = g_ekc + h*Cq*Sq;
  int base = (b*Tq + c*Cq)*Dq + h*Sq;
  for(int idx=tid; idx<Cq*Sq; idx+=256){
    int t=idx>>6, s=idx&63;
    kw[idx] = __fmul_rn(Yk[base + t*Dq + s], ekc[idx]);
    vs[idx] = Yv[base + t*Dq + s];
  }
  __syncthreads();
  int ts=(tid>>4)*4, to=(tid&15)*4;
  float acc[4][4]={};
  for(int t=0;t<Cq;t++){
    float4 a=*(const float4*)&kw[t*Sq+ts];
    float4 v=*(const float4*)&vs[t*Sq+to];
    acc[0][0]+=a.x*v.x; acc[0][1]+=a.x*v.y; acc[0][2]+=a.x*v.z; acc[0][3]+=a.x*v.w;
    acc[1][0]+=a.y*v.x; acc[1][1]+=a.y*v.y; acc[1][2]+=a.y*v.z; acc[1][3]+=a.y*v.w;
    acc[2][0]+=a.z*v.x; acc[2][1]+=a.z*v.y; acc[2][2]+=a.z*v.z; acc[2][3]+=a.z*v.w;
    acc[3][0]+=a.w*v.x; acc[3][1]+=a.w*v.y; acc[3][2]+=a.w*v.z; acc[3][3]+=a.w*v.w;
  }
  float* G = &g_states[(bh*NCq + c)*Sq*Sq];
  #pragma unroll
  for(int i=0;i<4;i++)
    #pragma unroll
    for(int jj=0;jj<4;jj++)
      G[(ts+i)*Sq + to+jj]=acc[i][jj];
}

// ---------------- WKV phase B: scan ----------------
__global__ void wkv_scan(){
  int bh = blockIdx.x, h = bh&15;
  int tid = threadIdx.x;
  __shared__ float wC[Sq];
  if(tid<Sq) wC[tid]=g_wCt[h*Sq+tid];
  __syncthreads();
  for(int e=tid; e<Sq*Sq; e+=256){
    float wc = wC[e>>6];
    float cur = 0.f;
    float* Gp = &g_states[bh*NCq*Sq*Sq + e];
    for(int c=0;c<NCq;c++){
      float gv = Gp[c*Sq*Sq];
      Gp[c*Sq*Sq]=cur;
      cur = __fadd_rn(__fmul_rn(wc,cur), gv);
    }
  }
}

// ---------------- WKV phase C: per-chunk output ----------------
__global__ void __launch_bounds__(256) wkv_main(){
  extern __shared__ float sm[];
  float* rpT = sm;               // [S][C] : r * w^{-t}
  float* rwT = sm + 4096;        // [S][C] : r * w^{t+1}
  float* kpT = sm + 8192;        // [S][C] : k * w^{t}
  float* vs  = sm + 12288;       // [C][S]
  float* st  = sm + 16384;       // [S][S] state before chunk
  float* PT  = sm + 20480;       // [C(i)][C(t)] masked
  __shared__ float uex[Sq], dv[Cq];

  int c = blockIdx.x, bh = blockIdx.y;
  int b = bh>>4, h = bh&15;
  int tid = threadIdx.x;
  if(tid<Sq) uex[tid]=g_uex[h*Sq+tid];
  const float* Yr=g_Y[0]; const float* Yk=g_Y[1]; const float* Yv=g_Y[2];
  const float* ein = g_ein + h*Cq*Sq;
  const float* ekt = g_ekt + h*Cq*Sq;
  const float* ek1 = g_ek1 + h*Cq*Sq;
  int base = (b*Tq + c*Cq)*Dq + h*Sq;
  const float* Gst = &g_states[(bh*NCq + c)*Sq*Sq];
  for(int idx=tid; idx<Cq*Sq; idx+=256){
    int t=idx>>6, s=idx&63;
    float rv=Yr[base + t*Dq + s];
    float kv=Yk[base + t*Dq + s];
    float vv=Yv[base + t*Dq + s];
    rpT[s*Cq+t]=__fmul_rn(rv,ein[idx]);
    rwT[s*Cq+t]=__fmul_rn(rv,ek1[idx]);
    kpT[s*Cq+t]=__fmul_rn(kv,ekt[idx]);
    vs[t*Sq+s]=vv;
    st[idx]=Gst[idx];
  }
  __syncthreads();
  if(tid<Cq){
    float a=0.f;
    for(int s=0;s<Sq;s++) a += rpT[s*Cq+tid]*kpT[s*Cq+tid]*uex[s];
    dv[tid]=a;
  }
  __syncthreads();
  int tt=(tid>>4)*4, ti=(tid&15)*4;
  {
    float acc[4][4]={};
    for(int s=0;s<Sq;s++){
      float4 a=*(const float4*)&rpT[s*Cq+tt];
      float4 k4=*(const float4*)&kpT[s*Cq+ti];
      acc[0][0]+=a.x*k4.x; acc[0][1]+=a.x*k4.y; acc[0][2]+=a.x*k4.z; acc[0][3]+=a.x*k4.w;
      acc[1][0]+=a.y*k4.x; acc[1][1]+=a.y*k4.y; acc[1][2]+=a.y*k4.z; acc[1][3]+=a.y*k4.w;
      acc[2][0]+=a.z*k4.x; acc[2][1]+=a.z*k4.y; acc[2][2]+=a.z*k4.z; acc[2][3]+=a.z*k4.w;
      acc[3][0]+=a.w*k4.x; acc[3][1]+=a.w*k4.y; acc[3][2]+=a.w*k4.z; acc[3][3]+=a.w*k4.w;
    }
    #pragma unroll
    for(int i=0;i<4;i++)
      #pragma unroll
      for(int jj=0;jj<4;jj++)
        PT[(ti+jj)*Cq + (tt+i)] = (ti+jj >= tt+i) ? acc[i][jj] : 0.f;
  }
  __syncthreads();
  int to = ti;
  {
    float acc[4][4]={};
    for(int l=0;l<Sq;l++){
      float4 a =*(const float4*)&PT[l*Cq+tt];
      float4 v4=*(const float4*)&vs[l*Sq+to];
      float4 r4=*(const float4*)&rwT[l*Cq+tt];
      float4 s4=*(const float4*)&st[l*Sq+to];
      acc[0][0]+=a.x*v4.x+r4.x*s4.x; acc[0][1]+=a.x*v4.y+r4.x*s4.y;
      acc[0][2]+=a.x*v4.z+r4.x*s4.z; acc[0][3]+=a.x*v4.w+r4.x*s4.w;
      acc[1][0]+=a.y*v4.x+r4.y*s4.x; acc[1][1]+=a.y*v4.y+r4.y*s4.y;
      acc[1][2]+=a.y*v4.z+r4.y*s4.z; acc[1][3]+=a.y*v4.w+r4.y*s4.w;
      acc[2][0]+=a.z*v4.x+r4.z*s4.x; acc[2][1]+=a.z*v4.y+r4.z*s4.y;
      acc[2][2]+=a.z*v4.z+r4.z*s4.z; acc[2][3]+=a.z*v4.w+r4.z*s4.w;
      acc[3][0]+=a.w*v4.x+r4.w*s4.x; acc[3][1]+=a.w*v4.y+r4.w*s4.y;
      acc[3][2]+=a.w*v4.z+r4.w*s4.z; acc[3][3]+=a.w*v4.w+r4.w*s4.w;
    }
    #pragma unroll
    for(int i=0;i<4;i++){
      float dd = dv[tt+i];
      #pragma unroll
      for(int jj=0;jj<4;jj++){
        float y = __fadd_rn(acc[i][jj], __fmul_rn(dd,vs[(tt+i)*Sq + to+jj]));
        g_ywkv[(b*Tq + c*Cq + tt+i)*Dq + h*Sq + to+jj] = y;
      }
    }
  }
}

// ---------------- GroupNorm + SiLU gate + LN + quant ----------------
__global__ void __launch_bounds__(256) gate_prep(
    const float* __restrict__ gn_g, const float* __restrict__ gn_b,
    const float* __restrict__ ln_g, const float* __restrict__ ln_b){
  int bt=blockIdx.x, tid=threadIdx.x, d0=tid<<2;
  __shared__ float yr[Dq], gm[Hq], gi[Hq];
  __shared__ float2 r1[8], r2[8];
  float4 y4 = *(const float4*)&g_ywkv[(size_t)bt*Dq + d0];
  *(float4*)&yr[d0] = y4;
  __syncthreads();
  int w=tid>>5, lane=tid&31;
  for(int gg=2*w; gg<2*w+2; gg++){
    float e1=yr[gg*Sq+lane], e2=yr[gg*Sq+32+lane];
    float2 s = df_comb(make_float2(e1,0.f), make_float2(e2,0.f));
    #pragma unroll
    for(int o=16;o;o>>=1) s = df_comb(s, shfl2(s,o));
    float m=__fmul_rn(s.x+s.y, 1.f/Sq);
    float d1=__fsub_rn(e1,m), d2=__fsub_rn(e2,m);
    float2 s2 = df_comb(make_float2(__fmul_rn(d1,d1),0.f), make_float2(__fmul_rn(d2,d2),0.f));
    #pragma unroll
    for(int o=16;o;o>>=1) s2 = df_comb(s2, shfl2(s2,o));
    if(lane==0){
      gm[gg]=m;
      float ve=__fadd_rn(__fmul_rn(s2.x+s2.y, 1.f/Sq), 1e-5f);
      gi[gg]=(float)(1.0/sqrt((double)ve));
    }
  }
  __syncthreads();
  int gg=d0>>6;
  float4 gg4=*(const float4*)&gn_g[d0];
  float4 gb4=*(const float4*)&gn_b[d0];
  float4 gv4=*(const float4*)&g_Y[3][(size_t)bt*Dq + d0];
  float mm=gm[gg], ii=gi[gg];
  float4 v4;
  {
    float yn=__fadd_rn(__fmul_rn(__fmul_rn(__fsub_rn(y4.x,mm),ii),gg4.x),gb4.x);
    float sg=__fdiv_rn(1.f,__fadd_rn(1.f,expf(-gv4.x)));
    v4.x=__fmul_rn(yn,__fmul_rn(gv4.x,sg));
    yn=__fadd_rn(__fmul_rn(__fmul_rn(__fsub_rn(y4.y,mm),ii),gg4.y),gb4.y);
    sg=__fdiv_rn(1.f,__fadd_rn(1.f,expf(-gv4.y)));
    v4.y=__fmul_rn(yn,__fmul_rn(gv4.y,sg));
    yn=__fadd_rn(__fmul_rn(__fmul_rn(__fsub_rn(y4.z,mm),ii),gg4.z),gb4.z);
    sg=__fdiv_rn(1.f,__fadd_rn(1.f,expf(-gv4.z)));
    v4.z=__fmul_rn(yn,__fmul_rn(gv4.z,sg));
    yn=__fadd_rn(__fmul_rn(__fmul_rn(__fsub_rn(y4.w,mm),ii),gg4.w),gb4.w);
    sg=__fdiv_rn(1.f,__fadd_rn(1.f,expf(-gv4.w)));
    v4.w=__fmul_rn(yn,__fmul_rn(gv4.w,sg));
  }
  ln_quant4(v4, ln_g+4*Dq, ln_b+4*Dq, 4, bt, r1, r2, tid);
}

// ---------------- launch ----------------
extern "C" void kernel_launch(void* const* d_in, const int* in_sizes, int n_in,
                              void* d_out, int out_size){
  const float* x        =(const float*)d_in[0];
  const float* mu_r     =(const float*)d_in[1];
  const float* mu_k     =(const float*)d_in[2];
  const float* mu_v     =(const float*)d_in[3];
  const float* mu_g     =(const float*)d_in[4];
  const float* log_decay=(const float*)d_in[5];
  const float* u        =(const float*)d_in[6];
  const float* proj_w   =(const float*)d_in[7];
  const float* ln_g     =(const float*)d_in[8];
  const float* ln_b     =(const float*)d_in[9];
  const float* gn_g     =(const float*)d_in[10];
  const float* gn_b     =(const float*)d_in[11];
  float* out=(float*)d_out;

  cudaFuncSetAttribute(wkv_main,  cudaFuncAttributeMaxDynamicSharedMemorySize, 98304);
  cudaFuncSetAttribute(gemm_hmma, cudaFuncAttributeMaxDynamicSharedMemorySize, 2*STG);

  // (0) weight abs-sum partials
  wq_part <<<dim3(64,5),256>>>(proj_w);
  // (1) token shift + LN + act quant for r,k,v,g
  prep_rkvg<<<dim3(NTq,4),256>>>(x,mu_r,mu_k,mu_v,mu_g,ln_g,ln_b);
  // (2) weight scale + quantize (fused)
  wq_quant<<<5120,256>>>(proj_w);
  // (3) 4 projection GEMMs, batched  <-- profiled launch index
  gemm_hmma<<<dim3(Dq/BROWS, NTq/AROWS, 4),256,2*STG>>>(0,out);

  // decay/exp tables (needed from wkv_contrib onward)
  build_tables<<<Hq,256>>>(log_decay,u);

  // WKV
  wkv_contrib<<<dim3(NCq,BHq),256>>>();
  wkv_scan   <<<BHq,256>>>();
  wkv_main   <<<dim3(NCq,BHq),256,98304>>>();

  // GroupNorm + gate + final LN/quant
  gate_prep<<<NTq,256>>>(gn_g,gn_b,ln_g,ln_b);

  // output projection GEMM -> d_out
  gemm_hmma<<<dim3(Dq/BROWS, NTq/AROWS, 1),256,2*STG>>>(4,out);
}

// round 15
// speedup vs baseline: 1.1860x; 1.0502x over previous
#include <cuda_runtime.h>
#include <cuda_bf16.h>
#include <stdint.h>

#define Bq 4
#define Tq 2048
#define Dq 1024
#define Hq 16
#define Sq 64
#define Cq 64
#define NTq (Bq*Tq)      // 8192 rows
#define NCq (Tq/Cq)      // 32 chunks
#define BHq (Bq*Hq)      // 64 (b,h) pairs
#define WP 68            // padded smem row stride (floats) for wkv_main tiles

// ---------------- scratch (static __device__, allocation-free) ----------------
__device__ __nv_bfloat16 g_Wb[5][Dq*Dq];   // ternary weights as bf16 (-1,0,1)
__device__ float  g_wpart[5][64];
__device__ float  g_wscale[5];
__device__ __nv_bfloat16 g_Xb[5][NTq*Dq];  // quantized activations as bf16 ints
__device__ float  g_xscale[5][NTq];
__device__ float  g_Y[4][NTq*Dq];          // r,k,v,g projection outputs (fp32)
__device__ float  g_states[BHq*NCq*Sq*Sq]; // per-chunk contributions -> states
__device__ float  g_ywkv[NTq*Dq];          // wkv output in (B,T,D)
// decay tables: [h][t][s], bit-exact replicas of the per-block exp computations
__device__ float  g_ein[Hq*Cq*Sq];         // exp(-t*lw)
__device__ float  g_ekt[Hq*Cq*Sq];         // exp(t*lw)
__device__ float  g_ek1[Hq*Cq*Sq];         // exp((t+1)*lw)
__device__ float  g_ekc[Hq*Cq*Sq];         // exp((C-1-t)*lw)
__device__ float  g_uex[Hq*Sq];            // exp(u)
__device__ float  g_wCt[Hq*Sq];            // exp(C*lw)

// ---------------- compensated-sum helpers ----------------
__device__ __forceinline__ float2 df_comb(float2 a, float2 b){
  float s  = a.x + b.x;
  float bp = s - a.x;
  float er = (a.x - (s - bp)) + (b.x - bp);
  return make_float2(s, a.y + b.y + er);
}
__device__ __forceinline__ void df_acc(float2& s, float v){
  float t=s.x+v; float bp=t-s.x; float er=(s.x-(t-bp))+(v-bp);
  s.x=t; s.y+=er;
}
__device__ __forceinline__ float2 shfl2(float2 v, int o){
  return make_float2(__shfl_xor_sync(0xffffffffu,v.x,o),
                     __shfl_xor_sync(0xffffffffu,v.y,o));
}
// 3-sync block reductions over 256 threads (8 warps)
__device__ __forceinline__ void block_sum2(float2& a, float2& b, float2* r1, float2* r2, int tid){
  #pragma unroll
  for(int o=16;o;o>>=1){ a=df_comb(a,shfl2(a,o)); b=df_comb(b,shfl2(b,o)); }
  __syncthreads();
  if((tid&31)==0){ r1[tid>>5]=a; r2[tid>>5]=b; }
  __syncthreads();
  if(tid<32){
    float2 aa=(tid<8)?r1[tid]:make_float2(0.f,0.f);
    float2 bb=(tid<8)?r2[tid]:make_float2(0.f,0.f);
    #pragma unroll
    for(int o=4;o;o>>=1){ aa=df_comb(aa,shfl2(aa,o)); bb=df_comb(bb,shfl2(bb,o)); }
    if(tid==0){ r1[0]=aa; r2[0]=bb; }
  }
  __syncthreads();
  a=r1[0]; b=r2[0];
}
__device__ __forceinline__ void block_sum1(float2& a, float2* r1, int tid){
  #pragma unroll
  for(int o=16;o;o>>=1) a=df_comb(a,shfl2(a,o));
  __syncthreads();
  if((tid&31)==0) r1[tid>>5]=a;
  __syncthreads();
  if(tid<32){
    float2 aa=(tid<8)?r1[tid]:make_float2(0.f,0.f);
    #pragma unroll
    for(int o=4;o;o>>=1) aa=df_comb(aa,shfl2(aa,o));
    if(tid==0) r1[0]=aa;
  }
  __syncthreads();
  a=r1[0];
}

// exp(n * lw) with exact hi/lo argument split: expf(hi)*(1+lo)
__device__ __forceinline__ float exp_nlw(float n, float lw){
  float hi = __fmul_rn(n, lw);
  float lo = __fmaf_rn(n, lw, -hi);
  return __fmul_rn(expf(hi), __fadd_rn(1.f, lo));
}

__device__ __forceinline__ uint32_t smem_u32(const void* p){
  return (uint32_t)__cvta_generic_to_shared(p);
}

// ---------------- decay table builder (once; bit-exact vs in-kernel formulas) ----
__global__ void build_tables(const float* __restrict__ ld_in, const float* __restrict__ u_in){
  int h = blockIdx.x, tid = threadIdx.x;
  __shared__ float lws[Sq];
  if(tid<Sq){
    float w = expf(-expf(ld_in[h*Sq+tid]));
    float lw = logf(fmaxf(w,1e-38f));
    lws[tid]=lw;
    g_uex[h*Sq+tid]=expf(u_in[h*Sq+tid]);
    g_wCt[h*Sq+tid]=expf(__fmul_rn((float)Cq,lw));
  }
  __syncthreads();
  for(int idx=tid; idx<Cq*Sq; idx+=256){
    int t=idx>>6, s=idx&63;
    float lw=lws[s];
    g_ein[h*Cq*Sq+idx]=exp_nlw(-(float)t, lw);
    g_ekt[h*Cq*Sq+idx]=exp_nlw((float)t, lw);
    g_ek1[h*Cq*Sq+idx]=exp_nlw((float)(t+1), lw);
    g_ekc[h*Cq*Sq+idx]=exp_nlw((float)(Cq-1-t), lw);
  }
}

// ---------------- LN + abs-mean + bf16-int quantize (4 elems/thread) ----------------
__device__ __forceinline__ void ln_quant4(float4 v4, const float* gp, const float* bp,
                                          int j, int bt, float2* r1, float2* r2, int tid){
  float ps = ((v4.x+v4.y)+(v4.z+v4.w));
  float pq = ((__fmul_rn(v4.x,v4.x)+__fmul_rn(v4.y,v4.y))
             +(__fmul_rn(v4.z,v4.z)+__fmul_rn(v4.w,v4.w)));
  float2 s1=make_float2(ps,0.f), s2=make_float2(pq,0.f);
  block_sum2(s1,s2,r1,r2,tid);
  if(tid==0){
    float m0 = __fmul_rn(__fadd_rn(s1.x,s1.y), 1.f/Dq);
    double S1=(double)s1.x+(double)s1.y, S2=(double)s2.x+(double)s2.y;
    double var = S2*(1.0/Dq) - (double)m0*(2.0*S1*(1.0/Dq) - (double)m0);
    float inv0 = (float)(1.0/sqrt(var + 1e-5));
    r2[1]=make_float2(m0,inv0);
  }
  __syncthreads();
  float m=r2[1].x, inv=r2[1].y;
  int d0=tid<<2;
  float4 g4=*(const float4*)&gp[d0];
  float4 b4=*(const float4*)&bp[d0];
  float n0=__fadd_rn(__fmul_rn(__fmul_rn(__fsub_rn(v4.x,m),inv),g4.x),b4.x);
  float n1=__fadd_rn(__fmul_rn(__fmul_rn(__fsub_rn(v4.y,m),inv),g4.y),b4.y);
  float n2=__fadd_rn(__fmul_rn(__fmul_rn(__fsub_rn(v4.z,m),inv),g4.z),b4.z);
  float n3=__fadd_rn(__fmul_rn(__fmul_rn(__fsub_rn(v4.w,m),inv),g4.w),b4.w);
  float2 sa=make_float2(((fabsf(n0)+fabsf(n1))+(fabsf(n2)+fabsf(n3))),0.f);
  block_sum1(sa,r1,tid);
  float am = __fmul_rn(__fadd_rn(sa.x,sa.y), 1.f/Dq);
  float scale = __fdiv_rn(__fmul_rn(fmaxf(am,1e-8f),2.5f), 127.f);
  float q0=rintf(fminf(fmaxf(__fdiv_rn(n0,scale),-127.f),127.f));
  float q1=rintf(fminf(fmaxf(__fdiv_rn(n1,scale),-127.f),127.f));
  float q2=rintf(fminf(fmaxf(__fdiv_rn(n2,scale),-127.f),127.f));
  float q3=rintf(fminf(fmaxf(__fdiv_rn(n3,scale),-127.f),127.f));
  union { __nv_bfloat16 h[4]; uint2 u; } o;
  o.h[0]=__float2bfloat16_rn(q0); o.h[1]=__float2bfloat16_rn(q1);
  o.h[2]=__float2bfloat16_rn(q2); o.h[3]=__float2bfloat16_rn(q3);
  *(uint2*)&g_Xb[j][(size_t)bt*Dq + d0] = o.u;
  if(tid==0) g_xscale[j][bt]=scale;
}

// ---------------- weight quantization ----------------
__global__ void wq_part(const float* __restrict__ pw){
  int j=blockIdx.y, sl=blockIdx.x, tid=threadIdx.x;
  __shared__ float2 r1[8];
  const float* w = pw + j*(Dq*Dq) + sl*16384;
  float2 s=make_float2(0.f,0.f);
  for(int i=tid;i<16384;i+=256) df_acc(s,fabsf(w[i]));
  block_sum1(s,r1,tid);
  if(tid==0) g_wpart[j][sl]=__fadd_rn(s.x,s.y);
}
// fused: computes the global scale (identical fp64 reduction) in thread 0, broadcast.
__global__ void wq_quant(const float* __restrict__ pw){
  __shared__ float sc_sh;
  int gi = blockIdx.x*1024 + threadIdx.x*4;
  int j  = gi >> 20;
  if(threadIdx.x==0){
    double s=0.0;
    for(int i=0;i<64;i++) s+=(double)g_wpart[j][i];
    float sc=fmaxf((float)(s*(1.0/(double)(Dq*Dq))),1e-8f);
    sc_sh=sc;
    g_wscale[j]=sc;
  }
  __syncthreads();
  float sc = sc_sh;
  float4 wv = *(const float4*)&pw[gi];
  union { __nv_bfloat16 h[4]; uint2 u; } o;
  o.h[0]=__float2bfloat16_rn(rintf(fminf(fmaxf(__fdiv_rn(wv.x,sc),-1.f),1.f)));
  o.h[1]=__float2bfloat16_rn(rintf(fminf(fmaxf(__fdiv_rn(wv.y,sc),-1.f),1.f)));
  o.h[2]=__float2bfloat16_rn(rintf(fminf(fmaxf(__fdiv_rn(wv.z,sc),-1.f),1.f)));
  o.h[3]=__float2bfloat16_rn(rintf(fminf(fmaxf(__fdiv_rn(wv.w,sc),-1.f),1.f)));
  *(uint2*)&(((__nv_bfloat16*)g_Wb)[gi]) = o.u;
}

// ---------------- token shift + LN + act quant (one block per (row, proj)) ----------------
__global__ void __launch_bounds__(256) prep_rkvg(
    const float* __restrict__ x,
    const float* __restrict__ mu_r, const float* __restrict__ mu_k,
    const float* __restrict__ mu_v, const float* __restrict__ mu_g,
    const float* __restrict__ ln_g, const float* __restrict__ ln_b){
  int bt=blockIdx.x, j=blockIdx.y;
  int t = bt & (Tq-1);
  int tid=threadIdx.x, d0=tid<<2;
  __shared__ float2 r1[8], r2[8];
  const float* mu = (j==0)?mu_r:(j==1)?mu_k:(j==2)?mu_v:mu_g;
  float4 xv = *(const float4*)&x[(size_t)bt*Dq + d0];
  float4 xp = (t==0)? make_float4(0.f,0.f,0.f,0.f)
                    : *(const float4*)&x[(size_t)(bt-1)*Dq + d0];
  float4 m4 = *(const float4*)&mu[d0];
  float4 v4;
  v4.x=__fadd_rn(xv.x,__fmul_rn(__fsub_rn(xp.x,xv.x),m4.x));
  v4.y=__fadd_rn(xv.y,__fmul_rn(__fsub_rn(xp.y,xv.y),m4.y));
  v4.z=__fadd_rn(xv.z,__fmul_rn(__fsub_rn(xp.z,xv.z),m4.z));
  v4.w=__fadd_rn(xv.w,__fmul_rn(__fsub_rn(xp.w,xv.w),m4.w));
  ln_quant4(v4, ln_g+j*Dq, ln_b+j*Dq, j, bt, r1, r2, tid);
}

// ---------------- HMMA bf16 GEMM: C[8192,1024] = Xb . Wb^T (exact int-in-bf16) ----------------
// CTA 64(M)x128(N), 8 warps as 2(M)x4(N), warp tile 32x32 (acc=32 regs),
// __launch_bounds__(256,4) -> 4 CTAs/SM = 32 warps.
#define RSTRIDE 144            // 128B row + 16B pad: LDSM phases conflict-free
#define AROWS 64
#define BROWS 128
#define NRWS (AROWS+BROWS)     // 192 rows per stage
#define STG (NRWS*RSTRIDE)     // 27648 B per stage; 2 stages = 55296
__device__ __forceinline__ void mma_bf16(float* d, uint32_t a0,uint32_t a1,uint32_t a2,uint32_t a3,
                                         uint32_t b0,uint32_t b1){
  asm volatile("mma.sync.aligned.m16n8k16.row.col.f32.bf16.bf16.f32 "
    "{%0,%1,%2,%3}, {%4,%5,%6,%7}, {%8,%9}, {%0,%1,%2,%3};"
    : "+f"(d[0]),"+f"(d[1]),"+f"(d[2]),"+f"(d[3])
    : "r"(a0),"r"(a1),"r"(a2),"r"(a3),"r"(b0),"r"(b1));
}
__device__ __forceinline__ void ldsm4(uint32_t& r0,uint32_t& r1,uint32_t& r2,uint32_t& r3,
                                      uint32_t addr){
  asm volatile("ldmatrix.sync.aligned.m8n8.x4.shared.b16 {%0,%1,%2,%3}, [%4];"
    : "=r"(r0),"=r"(r1),"=r"(r2),"=r"(r3) : "r"(addr));
}
__device__ __forceinline__ void cp16(uint32_t daddr, const void* gptr){
  asm volatile("cp.async.cg.shared.global [%0], [%1], 16;" :: "r"(daddr), "l"(gptr));
}
__global__ void __launch_bounds__(256,4) gemm_hmma(int jbase, float* __restrict__ dout){
  extern __shared__ char sm8[];
  int j = jbase + blockIdx.z;
  const __nv_bfloat16* Ag = g_Xb[j];
  const __nv_bfloat16* Bg = g_Wb[j];
  float* C = (j==4)? dout : g_Y[j];
  int tid=threadIdx.x;
  int wid=tid>>5, lane=tid&31;
  int g=lane>>2, tig=lane&3;
  int wm=wid>>2, wn=wid&3;                 // 2(M) x 4(N)
  int m0=blockIdx.y*AROWS, n0=blockIdx.x*BROWS;
  int lrow=lane&15, lhi=(lane>>4)*16;

  float acc[2][4][4];
  #pragma unroll
  for(int mi=0;mi<2;mi++)
    #pragma unroll
    for(int ni=0;ni<4;ni++)
      #pragma unroll
      for(int q=0;q<4;q++) acc[mi][ni][q]=0.f;

  // copy geometry (recomputed each prefetch; keeps only row/q in flight)
  int crow = tid>>3, cq = (tid&7)*16;      // 6 rows/thread stride 32
  // prologue: stage 0
  #pragma unroll
  for(int i=0;i<6;i++){
    int r = crow + i*32;
    const char* gb = (r<AROWS)
        ? (const char*)(Ag + (size_t)(m0+r)*Dq)
        : (const char*)(Bg + (size_t)(n0+(r-AROWS))*Dq);
    cp16(smem_u32(sm8 + r*RSTRIDE + cq), gb + cq);
  }
  asm volatile("cp.async.commit_group;");

  for(int kt=0;kt<16;kt++){
    asm volatile("cp.async.wait_group 0;");
    __syncthreads();                 // all warps done with buf^1 compute
    if(kt+1<16){
      uint32_t so = (uint32_t)(((kt+1)&1))*STG;
      int go = (kt+1)*128;
      #pragma unroll
      for(int i=0;i<6;i++){
        int r = crow + i*32;
        const char* gb = (r<AROWS)
            ? (const char*)(Ag + (size_t)(m0+r)*Dq)
            : (const char*)(Bg + (size_t)(n0+(r-AROWS))*Dq);
        cp16(smem_u32(sm8 + r*RSTRIDE + cq) + so, gb + cq + go);
      }
      asm volatile("cp.async.commit_group;");
    }
    const char* Ab = sm8 + (kt&1)*STG;
    const char* Bb = Ab + AROWS*RSTRIDE;
    #pragma unroll
    for(int s=0;s<4;s++){
      uint32_t af[2][4];
      #pragma unroll
      for(int mi=0;mi<2;mi++){
        uint32_t ad = smem_u32(Ab + (wm*32+mi*16+lrow)*RSTRIDE + s*32 + lhi);
        ldsm4(af[mi][0],af[mi][1],af[mi][2],af[mi][3], ad);
      }
      uint32_t b0a[4], b1a[4];
      #pragma unroll
      for(int nb2=0;nb2<2;nb2++){
        uint32_t bd = smem_u32(Bb + (wn*32+nb2*16+lrow)*RSTRIDE + s*32 + lhi);
        uint32_t r0,r1,r2,r3;
        ldsm4(r0,r1,r2,r3, bd);
        b0a[2*nb2]=r0; b0a[2*nb2+1]=r1; b1a[2*nb2]=r2; b1a[2*nb2+1]=r3;
      }
      #pragma unroll
      for(int mi=0;mi<2;mi++)
        #pragma unroll
        for(int ni=0;ni<4;ni++)
          mma_bf16(acc[mi][ni], af[mi][0],af[mi][1],af[mi][2],af[mi][3],
                   b0a[ni], b1a[ni]);
    }
  }

  float ws=g_wscale[j];
  #pragma unroll
  for(int mi=0;mi<2;mi++){
    int r0 = m0 + wm*32 + mi*16 + g;
    float sc0=__fmul_rn(g_xscale[j][r0  ],ws);
    float sc1=__fmul_rn(g_xscale[j][r0+8],ws);
    #pragma unroll
    for(int ni=0;ni<4;ni++){
      int col = n0 + wn*32 + ni*8 + tig*2;
      float2 o0, o1;
      o0.x=__fmul_rn(acc[mi][ni][0],sc0);
      o0.y=__fmul_rn(acc[mi][ni][1],sc0);
      o1.x=__fmul_rn(acc[mi][ni][2],sc1);
      o1.y=__fmul_rn(acc[mi][ni][3],sc1);
      *(float2*)&C[(size_t)r0*Dq + col]     = o0;
      *(float2*)&C[(size_t)(r0+8)*Dq + col] = o1;
    }
  }
}

// ---------------- WKV phase A: per-chunk contribution G_c = (K .* w^{C-1-t})^T @ V ----------------
__global__ void wkv_contrib(){
  int c = blockIdx.x, bh = blockIdx.y;
  int b = bh>>4, h = bh&15;
  int tid = threadIdx.x;
  __shared__ float kw[Cq*Sq], vs[Cq*Sq];
  const float* Yk = g_Y[1];
  const float* Yv = g_Y[2];
  const float* ekc = g_ekc + h*Cq*Sq;
  int base = (b*Tq + c*Cq)*Dq + h*Sq;
  for(int idx=tid; idx<Cq*Sq; idx+=256){
    int t=idx>>6, s=idx&63;
    kw[idx] = __fmul_rn(Yk[base + t*Dq + s], ekc[idx]);
    vs[idx] = Yv[base + t*Dq + s];
  }
  __syncthreads();
  int ts=(tid>>4)*4, to=(tid&15)*4;
  float acc[4][4]={};
  for(int t=0;t<Cq;t++){
    float4 a=*(const float4*)&kw[t*Sq+ts];
    float4 v=*(const float4*)&vs[t*Sq+to];
    acc[0][0]+=a.x*v.x; acc[0][1]+=a.x*v.y; acc[0][2]+=a.x*v.z; acc[0][3]+=a.x*v.w;
    acc[1][0]+=a.y*v.x; acc[1][1]+=a.y*v.y; acc[1][2]+=a.y*v.z; acc[1][3]+=a.y*v.w;
    acc[2][0]+=a.z*v.x; acc[2][1]+=a.z*v.y; acc[2][2]+=a.z*v.z; acc[2][3]+=a.z*v.w;
    acc[3][0]+=a.w*v.x; acc[3][1]+=a.w*v.y; acc[3][2]+=a.w*v.z; acc[3][3]+=a.w*v.w;
  }
  float* G = &g_states[(bh*NCq + c)*Sq*Sq];
  #pragma unroll
  for(int i=0;i<4;i++)
    #pragma unroll
    for(int jj=0;jj<4;jj++)
      G[(ts+i)*Sq + to+jj]=acc[i][jj];
}

// ---------------- WKV phase B: scan ----------------
__global__ void wkv_scan(){
  int bh = blockIdx.x, h = bh&15;
  int tid = threadIdx.x;
  __shared__ float wC[Sq];
  if(tid<Sq) wC[tid]=g_wCt[h*Sq+tid];
  __syncthreads();
  for(int e=tid; e<Sq*Sq; e+=256){
    float wc = wC[e>>6];
    float cur = 0.f;
    float* Gp = &g_states[bh*NCq*Sq*Sq + e];
    for(int c=0;c<NCq;c++){
      float gv = Gp[c*Sq*Sq];
      Gp[c*Sq*Sq]=cur;
      cur = __fadd_rn(__fmul_rn(wc,cur), gv);
    }
  }
}

// ---------------- WKV phase C: per-chunk output (PAD-68 conflict-free layout) ----------------
__global__ void __launch_bounds__(256) wkv_main(){
  extern __shared__ float sm[];
  float* rpT = sm;               // [S][C] pad WP : r * w^{-t}
  float* rwT = sm + Sq*WP;       // [S][C] pad WP : r * w^{t+1}
  float* kpT = sm + 2*Sq*WP;     // [S][C] pad WP : k * w^{t}
  float* vs  = sm + 3*Sq*WP;     // [C][S] pad WP
  float* st  = sm + 4*Sq*WP;     // [S][S] pad WP : state before chunk
  float* PT  = sm + 5*Sq*WP;     // [C(i)][C(t)] pad WP, masked
  __shared__ float uex[Sq], dv[Cq];

  int c = blockIdx.x, bh = blockIdx.y;
  int b = bh>>4, h = bh&15;
  int tid = threadIdx.x;
  if(tid<Sq) uex[tid]=g_uex[h*Sq+tid];
  const float* Yr=g_Y[0]; const float* Yk=g_Y[1]; const float* Yv=g_Y[2];
  const float* ein = g_ein + h*Cq*Sq;
  const float* ekt = g_ekt + h*Cq*Sq;
  const float* ek1 = g_ek1 + h*Cq*Sq;
  int base = (b*Tq + c*Cq)*Dq + h*Sq;
  const float* Gst = &g_states[(bh*NCq + c)*Sq*Sq];
  for(int idx=tid; idx<Cq*Sq; idx+=256){
    int t=idx>>6, s=idx&63;
    float rv=Yr[base + t*Dq + s];
    float kv=Yk[base + t*Dq + s];
    float vv=Yv[base + t*Dq + s];
    rpT[s*WP+t]=__fmul_rn(rv,ein[idx]);
    rwT[s*WP+t]=__fmul_rn(rv,ek1[idx]);
    kpT[s*WP+t]=__fmul_rn(kv,ekt[idx]);
    vs[t*WP+s]=vv;
    st[t*WP+s]=Gst[idx];        // t here is the S-row index of the state
  }
  __syncthreads();
  if(tid<Cq){
    float a=0.f;
    for(int s=0;s<Sq;s++) a += rpT[s*WP+tid]*kpT[s*WP+tid]*uex[s];
    dv[tid]=a;
  }
  __syncthreads();
  // first gemm: P[t][i] = (i>=t) sum_s rp[s][t]*kp[s][i]; thread covers t in tA..+3, i in iA..+3
  // (role-swapped vs before so PT row index spans 16 values/warp -> low-conflict writes)
  int tA=(tid&15)*4, iA=(tid>>4)*4;
  {
    float acc[4][4]={};    // acc[p][q] : t=tA+p, i=iA+q
    for(int s=0;s<Sq;s++){
      float4 a=*(const float4*)&rpT[s*WP+tA];
      float4 k4=*(const float4*)&kpT[s*WP+iA];
      acc[0][0]+=a.x*k4.x; acc[0][1]+=a.x*k4.y; acc[0][2]+=a.x*k4.z; acc[0][3]+=a.x*k4.w;
      acc[1][0]+=a.y*k4.x; acc[1][1]+=a.y*k4.y; acc[1][2]+=a.y*k4.z; acc[1][3]+=a.y*k4.w;
      acc[2][0]+=a.z*k4.x; acc[2][1]+=a.z*k4.y; acc[2][2]+=a.z*k4.z; acc[2][3]+=a.z*k4.w;
      acc[3][0]+=a.w*k4.x; acc[3][1]+=a.w*k4.y; acc[3][2]+=a.w*k4.z; acc[3][3]+=a.w*k4.w;
    }
    #pragma unroll
    for(int p=0;p<4;p++)
      #pragma unroll
      for(int q=0;q<4;q++)
        PT[(iA+q)*WP + (tA+p)] = (iA+q >= tA+p) ? acc[p][q] : 0.f;
  }
  __syncthreads();
  int tt=(tid>>4)*4, to=(tid&15)*4;
  {
    float acc[4][4]={};
    for(int l=0;l<Sq;l++){
      float4 a =*(const float4*)&PT[l*WP+tt];
      float4 v4=*(const float4*)&vs[l*WP+to];
      float4 r4=*(const float4*)&rwT[l*WP+tt];
      float4 s4=*(const float4*)&st[l*WP+to];
      acc[0][0]+=a.x*v4.x+r4.x*s4.x; acc[0][1]+=a.x*v4.y+r4.x*s4.y;
      acc[0][2]+=a.x*v4.z+r4.x*s4.z; acc[0][3]+=a.x*v4.w+r4.x*s4.w;
      acc[1][0]+=a.y*v4.x+r4.y*s4.x; acc[1][1]+=a.y*v4.y+r4.y*s4.y;
      acc[1][2]+=a.y*v4.z+r4.y*s4.z; acc[1][3]+=a.y*v4.w+r4.y*s4.w;
      acc[2][0]+=a.z*v4.x+r4.z*s4.x; acc[2][1]+=a.z*v4.y+r4.z*s4.y;
      acc[2][2]+=a.z*v4.z+r4.z*s4.z; acc[2][3]+=a.z*v4.w+r4.z*s4.w;
      acc[3][0]+=a.w*v4.x+r4.w*s4.x; acc[3][1]+=a.w*v4.y+r4.w*s4.y;
      acc[3][2]+=a.w*v4.z+r4.w*s4.z; acc[3][3]+=a.w*v4.w+r4.w*s4.w;
    }
    #pragma unroll
    for(int i=0;i<4;i++){
      float dd = dv[tt+i];
      #pragma unroll
      for(int jj=0;jj<4;jj++){
        float y = __fadd_rn(acc[i][jj], __fmul_rn(dd,vs[(tt+i)*WP + to+jj]));
        g_ywkv[(b*Tq + c*Cq + tt+i)*Dq + h*Sq + to+jj] = y;
      }
    }
  }
}

// ---------------- GroupNorm + SiLU gate + LN + quant ----------------
__global__ void __launch_bounds__(256) gate_prep(
    const float* __restrict__ gn_g, const float* __restrict__ gn_b,
    const float* __restrict__ ln_g, const float* __restrict__ ln_b){
  int bt=blockIdx.x, tid=threadIdx.x, d0=tid<<2;
  __shared__ float yr[Dq], gm[Hq], gi[Hq];
  __shared__ float2 r1[8], r2[8];
  float4 y4 = *(const float4*)&g_ywkv[(size_t)bt*Dq + d0];
  *(float4*)&yr[d0] = y4;
  __syncthreads();
  int w=tid>>5, lane=tid&31;
  for(int gg=2*w; gg<2*w+2; gg++){
    float e1=yr[gg*Sq+lane], e2=yr[gg*Sq+32+lane];
    float2 s = df_comb(make_float2(e1,0.f), make_float2(e2,0.f));
    #pragma unroll
    for(int o=16;o;o>>=1) s = df_comb(s, shfl2(s,o));
    float m=__fmul_rn(s.x+s.y, 1.f/Sq);
    float d1=__fsub_rn(e1,m), d2=__fsub_rn(e2,m);
    float2 s2 = df_comb(make_float2(__fmul_rn(d1,d1),0.f), make_float2(__fmul_rn(d2,d2),0.f));
    #pragma unroll
    for(int o=16;o;o>>=1) s2 = df_comb(s2, shfl2(s2,o));
    if(lane==0){
      gm[gg]=m;
      float ve=__fadd_rn(__fmul_rn(s2.x+s2.y, 1.f/Sq), 1e-5f);
      gi[gg]=(float)(1.0/sqrt((double)ve));
    }
  }
  __syncthreads();
  int gg=d0>>6;
  float4 gg4=*(const float4*)&gn_g[d0];
  float4 gb4=*(const float4*)&gn_b[d0];
  float4 gv4=*(const float4*)&g_Y[3][(size_t)bt*Dq + d0];
  float mm=gm[gg], ii=gi[gg];
  float4 v4;
  {
    float yn=__fadd_rn(__fmul_rn(__fmul_rn(__fsub_rn(y4.x,mm),ii),gg4.x),gb4.x);
    float sg=__fdiv_rn(1.f,__fadd_rn(1.f,expf(-gv4.x)));
    v4.x=__fmul_rn(yn,__fmul_rn(gv4.x,sg));
    yn=__fadd_rn(__fmul_rn(__fmul_rn(__fsub_rn(y4.y,mm),ii),gg4.y),gb4.y);
    sg=__fdiv_rn(1.f,__fadd_rn(1.f,expf(-gv4.y)));
    v4.y=__fmul_rn(yn,__fmul_rn(gv4.y,sg));
    yn=__fadd_rn(__fmul_rn(__fmul_rn(__fsub_rn(y4.z,mm),ii),gg4.z),gb4.z);
    sg=__fdiv_rn(1.f,__fadd_rn(1.f,expf(-gv4.z)));
    v4.z=__fmul_rn(yn,__fmul_rn(gv4.z,sg));
    yn=__fadd_rn(__fmul_rn(__fmul_rn(__fsub_rn(y4.w,mm),ii),gg4.w),gb4.w);
    sg=__fdiv_rn(1.f,__fadd_rn(1.f,expf(-gv4.w)));
    v4.w=__fmul_rn(yn,__fmul_rn(gv4.w,sg));
  }
  ln_quant4(v4, ln_g+4*Dq, ln_b+4*Dq, 4, bt, r1, r2, tid);
}

// ---------------- launch ----------------
extern "C" void kernel_launch(void* const* d_in, const int* in_sizes, int n_in,
                              void* d_out, int out_size){
  const float* x        =(const float*)d_in[0];
  const float* mu_r     =(const float*)d_in[1];
  const float* mu_k     =(const float*)d_in[2];
  const float* mu_v     =(const float*)d_in[3];
  const float* mu_g     =(const float*)d_in[4];
  const float* log_decay=(const float*)d_in[5];
  const float* u        =(const float*)d_in[6];
  const float* proj_w   =(const float*)d_in[7];
  const float* ln_g     =(const float*)d_in[8];
  const float* ln_b     =(const float*)d_in[9];
  const float* gn_g     =(const float*)d_in[10];
  const float* gn_b     =(const float*)d_in[11];
  float* out=(float*)d_out;

  const int wkv_smem = 6*Sq*WP*4;   // 104448 bytes
  cudaFuncSetAttribute(wkv_main,  cudaFuncAttributeMaxDynamicSharedMemorySize, wkv_smem);
  cudaFuncSetAttribute(gemm_hmma, cudaFuncAttributeMaxDynamicSharedMemorySize, 2*STG);

  // (0) weight abs-sum partials
  wq_part <<<dim3(64,5),256>>>(proj_w);
  // (1) token shift + LN + act quant for r,k,v,g
  prep_rkvg<<<dim3(NTq,4),256>>>(x,mu_r,mu_k,mu_v,mu_g,ln_g,ln_b);
  // (2) weight scale + quantize (fused)
  wq_quant<<<5120,256>>>(proj_w);
  // (3) 4 projection GEMMs, batched  <-- profiled launch index
  gemm_hmma<<<dim3(Dq/BROWS, NTq/AROWS, 4),256,2*STG>>>(0,out);

  // decay/exp tables (needed from wkv_contrib onward)
  build_tables<<<Hq,256>>>(log_decay,u);

  // WKV
  wkv_contrib<<<dim3(NCq,BHq),256>>>();
  wkv_scan   <<<BHq,256>>>();
  wkv_main   <<<dim3(NCq,BHq),256,wkv_smem>>>();

  // GroupNorm + gate + final LN/quant
  gate_prep<<<NTq,256>>>(gn_g,gn_b,ln_g,ln_b);

  // output projection GEMM -> d_out
  gemm_hmma<<<dim3(Dq/BROWS, NTq/AROWS, 1),256,2*STG>>>(4,out);
}